// round 11
// baseline (speedup 1.0000x reference)
#include <cuda_runtime.h>
#include <math.h>

// Problem constants
#define HH 32
#define WW 32
#define PP 64
#define UU 64
#define LL 32
#define BB 8
#define NF 256          // L*B frames
#define NFX 264         // + 8 x0 frames
#define FRAME 65536     // 32*32*64 elements per frame-channel block

typedef unsigned long long u64;

// single dynamic-smem symbol shared by all kernels
extern __shared__ char s_raw[];

// ---------------- packed f32x2 helpers --------------------------------------
__device__ __forceinline__ u64 fma2(u64 a, u64 b, u64 c) {
    u64 d;
    asm("fma.rn.f32x2 %0, %1, %2, %3;" : "=l"(d) : "l"(a), "l"(b), "l"(c));
    return d;
}
__device__ __forceinline__ void unpack2(u64 v, float& lo, float& hi) {
    asm("mov.b64 {%0, %1}, %2;" : "=f"(lo), "=f"(hi) : "l"(v));
}

// multiply by (-i)^k
__device__ __forceinline__ float2 rot_negi(float2 x, int k) {
    switch (k & 3) {
        case 0: return x;
        case 1: return make_float2(x.y, -x.x);
        case 2: return make_float2(-x.x, -x.y);
        default: return make_float2(-x.y, x.x);
    }
}
// multiply by i^k
__device__ __forceinline__ float2 rot_posi(float2 x, int k) {
    switch (k & 3) {
        case 0: return x;
        case 1: return make_float2(-x.y, x.x);
        case 2: return make_float2(-x.x, -x.y);
        default: return make_float2(x.y, -x.x);
    }
}

// ---------------- scratch (device globals; no allocation allowed) -------------
__device__ float2 g_Bu[(size_t)NFX * FRAME];   // conv-B output; later reused as
                                               // float scratch for conv-C partials
__device__ float2 g_sp[(size_t)NF * FRAME];    // spectral b_elems -> scan output (in-place)
__device__ float2 g_x0t[(size_t)BB * FRAME];   // B_coeff * transform(B x0)
__device__ float2 g_xri[(size_t)NF * FRAME];   // (Re, Im) of x_sp, interleaved
__device__ float2 g_Abar[FRAME];               // [h][w][p] (== [a][c][p])
__device__ float2 g_Bcoef[FRAME];
__device__ float2 g_Sdup[1024];                // real DST matrix S[m][n], duplicated (s,s)
__device__ float4 g_Wb4[9 * 32 * 64];          // [tap][cp][p]: (Br[2cp],Bi[2cp],Br[2cp+1],Bi[2cp+1])
__device__ float4 g_Wc4[9 * 32 * 64];          // [tap][cp][uo]: (2Cr,-2Ci for ci, then ci+1)
__device__ float4 g_Wd4[9 * 16 * 64];          // [tap][cq][uo]: Dk for 4 consecutive ci

// ---------------- K0a: S matrix (real symmetric DST core) -------------------
__global__ void k_precompute_q() {
    int i = threadIdx.x;           // 0..1023
    int m = i / 32 + 1, n = i % 32 + 1;
    double s = sin(M_PI * (double)m * (double)n / 33.0) / sqrt(16.5);
    g_Sdup[i] = make_float2((float)s, (float)s);
}

// ---------------- K0b: A_bar, B_coeff ---------------------------------------
__global__ void k_precompute_ab(const float* __restrict__ Lre,
                                const float* __restrict__ Lim,
                                const float* __restrict__ values,
                                const float* __restrict__ log_step) {
    int idx = blockIdx.x * 256 + threadIdx.x;   // [h][w][p]
    int p = idx & 63, w = (idx >> 6) & 31, h = idx >> 11;

    float v0 = values[p * 4 + 0], v1 = values[p * 4 + 1];
    float v2 = values[p * 4 + 2], v3 = values[p * 4 + 3];
    float mx = fmaxf(fmaxf(v0, v1), fmaxf(v2, v3));
    float e0 = expf(v0 - mx), e1 = expf(v1 - mx), e2 = expf(v2 - mx), e3 = expf(v3 - mx);
    float inv = 4.f / (e0 + e1 + e2 + e3);
    float xk = e0 * inv, yk = e1 * inv, zk = e2 * inv, wk = e3 * inv;
    float kv0 = (xk + yk - 2.f) * 0.25f;
    float kv1 = (xk + zk - 2.f) * 0.25f;
    float kv2 = (xk + wk - 2.f) * 0.125f;

    double ch = 2.0 * cos(M_PI * (double)(h + 1) / 33.0);
    double cw = 2.0 * cos(M_PI * (double)(w + 1) / 33.0);
    float Dv = kv0 * (float)cw + kv1 * (float)ch + kv2 * (float)(ch * cw) + 1.f;

    float lre = fminf(Lre[p], -1e-4f);
    float lim = Lim[p];
    float st = expf(log_step[p]);

    float tre = lre * Dv, tim = lim * Dv;
    float er = expf(tre * st);
    float Ar = er * cosf(tim * st);
    float Ai = er * sinf(tim * st);
    g_Abar[idx] = make_float2(Ar, Ai);

    float den = tre * tre + tim * tim;
    float br = ((Ar - 1.f) * tre + Ai * tim) / den;
    float bi = (Ai * tre - (Ar - 1.f) * tim) / den;
    g_Bcoef[idx] = make_float2(br, bi);
}

// ---------------- K0c/K0d/K0e: weight packing (ci-pair float4) --------------
__global__ void k_pack_b(const float* __restrict__ Br, const float* __restrict__ Bi) {
    int i = blockIdx.x * 256 + threadIdx.x;     // 0..18431 [tap][cp][p]
    int p = i & 63, cp = (i >> 6) & 31, tap = i >> 11;
    int i0 = (tap * 64 + 2 * cp) * 64 + p;
    g_Wb4[i] = make_float4(Br[i0], Bi[i0], Br[i0 + 64], Bi[i0 + 64]);
}
__global__ void k_pack_c(const float* __restrict__ Cr, const float* __restrict__ Ci) {
    int i = blockIdx.x * 256 + threadIdx.x;     // [tap][cp][uo]
    int uo = i & 63, cp = (i >> 6) & 31, tap = i >> 11;
    int i0 = (tap * 64 + 2 * cp) * 64 + uo;
    g_Wc4[i] = make_float4(2.f * Cr[i0], -2.f * Ci[i0],
                           2.f * Cr[i0 + 64], -2.f * Ci[i0 + 64]);
}
__global__ void k_pack_d(const float* __restrict__ Dk) {
    int i = blockIdx.x * 256 + threadIdx.x;     // 0..9215 [tap][cq][uo]
    int uo = i & 63, cq = (i >> 6) & 15, tap = i >> 10;
    int i0 = (tap * 64 + 4 * cq) * 64 + uo;
    g_Wd4[i] = make_float4(Dk[i0], Dk[i0 + 64], Dk[i0 + 128], Dk[i0 + 192]);
}

// ---------------- K1: conv B (complex, fma2, 2 output rows per block) -------
// block = (row-pair h0, frame f), 256 threads: thread = (p = t&63, wgroup = t>>6)
__global__ void __launch_bounds__(256, 2) conv_b_kernel(const float* __restrict__ u,
                                                        const float* __restrict__ x0) {
    int h0 = blockIdx.x * 2, f = blockIdx.y;
    const float* src = (f < NF) ? (u + (size_t)f * FRAME)
                                : (x0 + (size_t)(f - NF) * FRAME);
    float2* sdup = (float2*)s_raw;              // [4][34][64] duplicated values
    int t = threadIdx.x;
    for (int i = t; i < 4 * 34 * 64; i += 256) {
        int rr = i / 2176, rem = i % 2176;
        int wp = rem >> 6, ch = rem & 63;
        int hi = h0 - 1 + rr;
        float v = 0.f;
        if (hi >= 0 && hi < HH && wp >= 1 && wp <= 32)
            v = src[((size_t)hi * 32 + (wp - 1)) * 64 + ch];
        sdup[i] = make_float2(v, v);
    }
    __syncthreads();

    int p = t & 63, wg = t >> 6, w0 = wg * 8;
    u64 acc0[8], acc1[8];
#pragma unroll
    for (int j = 0; j < 8; j++) { acc0[j] = 0ull; acc1[j] = 0ull; }

    const ulonglong2* sd = (const ulonglong2*)sdup;   // [rr][wp][cp]
    const ulonglong2* wb = (const ulonglong2*)g_Wb4;
    for (int cp = 0; cp < 32; cp++) {
        ulonglong2 wv[9];
#pragma unroll
        for (int k = 0; k < 9; k++)
            wv[k] = __ldg(&wb[(k * 32 + cp) * 64 + p]);
#pragma unroll
        for (int rr = 0; rr < 4; rr++) {
            const ulonglong2* row = sd + (rr * 34 + w0) * 32;
            ulonglong2 xv[10];
#pragma unroll
            for (int m = 0; m < 10; m++) xv[m] = row[m * 32 + cp];
            if (rr < 3) {
#pragma unroll
                for (int dx = 0; dx < 3; dx++)
#pragma unroll
                    for (int j = 0; j < 8; j++) {
                        acc0[j] = fma2(xv[j + dx].x, wv[rr * 3 + dx].x, acc0[j]);
                        acc0[j] = fma2(xv[j + dx].y, wv[rr * 3 + dx].y, acc0[j]);
                    }
            }
            if (rr > 0) {
#pragma unroll
                for (int dx = 0; dx < 3; dx++)
#pragma unroll
                    for (int j = 0; j < 8; j++) {
                        acc1[j] = fma2(xv[j + dx].x, wv[(rr - 1) * 3 + dx].x, acc1[j]);
                        acc1[j] = fma2(xv[j + dx].y, wv[(rr - 1) * 3 + dx].y, acc1[j]);
                    }
            }
        }
    }
    u64* dst0 = (u64*)(g_Bu + (size_t)f * FRAME + (size_t)h0 * 32 * 64);
    u64* dst1 = dst0 + 32 * 64;
#pragma unroll
    for (int j = 0; j < 8; j++) {
        dst0[(w0 + j) * 64 + p] = acc0[j];
        dst1[(w0 + j) * 64 + p] = acc1[j];
    }
}

// ---------------- K2: forward transform (real-S two-sided) + B_coeff --------
// 256 threads: hg = t>>5 (8 values), c0 = (t&7)*4, j = (t>>3)&3.
// Register tile 4(hh) x 4(cc), one j per thread.
__global__ void __launch_bounds__(256, 2) fwd_transform_kernel() {
    float2* Xs = (float2*)s_raw;        // 4096
    float2* Ms = Xs + 4096;             // 4096
    float2* Sd = Ms + 4096;             // 1024
    int f = blockIdx.y;
    int p0 = blockIdx.x * 4;
    int t = threadIdx.x;

    for (int i = t; i < 1024; i += 256) Sd[i] = g_Sdup[i];
    const float2* src = g_Bu + (size_t)f * FRAME + p0;
    for (int i = t; i < 4096; i += 256) {
        int j = i & 3, hw = i >> 2;
        int h = hw >> 5, w = hw & 31;
        Xs[i] = rot_negi(src[(size_t)hw * 64 + j], h + w + 2);
    }
    __syncthreads();

    int hg = t >> 5;
    int c0 = (t & 7) * 4, j = (t >> 3) & 3;
    const u64* sXs = (const u64*)Xs;
    const u64* sSd = (const u64*)Sd;
    u64* sMs = (u64*)Ms;

    {
        u64 acc[4][4];
#pragma unroll
        for (int a1 = 0; a1 < 4; a1++)
#pragma unroll
            for (int a2 = 0; a2 < 4; a2++) acc[a1][a2] = 0ull;

        for (int w = 0; w < 32; w++) {
            u64 sv[4];
#pragma unroll
            for (int cc = 0; cc < 4; cc++) sv[cc] = sSd[w * 32 + c0 + cc];
            u64 xv[4];
#pragma unroll
            for (int hh = 0; hh < 4; hh++)
                xv[hh] = sXs[((hg + 8 * hh) * 32 + w) * 4 + j];
#pragma unroll
            for (int hh = 0; hh < 4; hh++)
#pragma unroll
                for (int cc = 0; cc < 4; cc++)
                    acc[hh][cc] = fma2(xv[hh], sv[cc], acc[hh][cc]);
        }
#pragma unroll
        for (int hh = 0; hh < 4; hh++)
#pragma unroll
            for (int cc = 0; cc < 4; cc++)
                sMs[((hg + 8 * hh) * 32 + c0 + cc) * 4 + j] = acc[hh][cc];
    }
    __syncthreads();

    bool isx0 = (f >= NF);
    float2* dst = isx0 ? g_x0t : g_sp;
    size_t base = isx0 ? (size_t)(f - NF) * FRAME : (size_t)f * FRAME;

    {
        u64 acc[4][4];
#pragma unroll
        for (int a1 = 0; a1 < 4; a1++)
#pragma unroll
            for (int a2 = 0; a2 < 4; a2++) acc[a1][a2] = 0ull;

        for (int h = 0; h < 32; h++) {
            u64 sv[4];
#pragma unroll
            for (int aa = 0; aa < 4; aa++) sv[aa] = sSd[h * 32 + hg + 8 * aa];
            u64 mv[4];
#pragma unroll
            for (int cc = 0; cc < 4; cc++)
                mv[cc] = sMs[(h * 32 + c0 + cc) * 4 + j];
#pragma unroll
            for (int aa = 0; aa < 4; aa++)
#pragma unroll
                for (int cc = 0; cc < 4; cc++)
                    acc[aa][cc] = fma2(mv[cc], sv[aa], acc[aa][cc]);
        }
#pragma unroll
        for (int aa = 0; aa < 4; aa++)
#pragma unroll
            for (int cc = 0; cc < 4; cc++) {
                int a = hg + 8 * aa, c = c0 + cc;
                int acp = (a * 32 + c) * 64 + p0 + j;
                float xr, xi;
                unpack2(acc[aa][cc], xr, xi);
                float2 bc = g_Bcoef[acp];
                dst[base + acp] = make_float2(xr * bc.x - xi * bc.y,
                                              xr * bc.y + xi * bc.x);
            }
    }
}

// ---------------- K3: linear recurrence over L (in place) -------------------
__global__ void scan_kernel() {
    int idx = blockIdx.x * 256 + threadIdx.x;   // 0..524287 = (b, acp)
    int b = idx >> 16;
    int acp = idx & 65535;
    float2 A = g_Abar[acp];
    float2 x = g_x0t[((size_t)b << 16) + acp];
    for (int l = 0; l < LL; l++) {
        size_t off = ((size_t)(l * BB + b) << 16) + acp;
        float2 v = g_sp[off];
        float2 nx;
        nx.x = A.x * x.x - A.y * x.y + v.x;
        nx.y = A.x * x.y + A.y * x.x + v.y;
        x = nx;
        g_sp[off] = x;
    }
}

// ---------------- K4: inverse transform (real-S two-sided), 256 threads -----
__global__ void __launch_bounds__(256, 2) inv_transform_kernel() {
    float2* Xs = (float2*)s_raw;
    float2* Ms = Xs + 4096;
    float2* Sd = Ms + 4096;
    int f = blockIdx.y;
    int p0 = blockIdx.x * 4;
    int t = threadIdx.x;

    for (int i = t; i < 1024; i += 256) Sd[i] = g_Sdup[i];
    const float2* src = g_sp + (size_t)f * FRAME + p0;
    for (int i = t; i < 4096; i += 256) {
        int j = i & 3, ac = i >> 2;
        Xs[i] = src[(size_t)ac * 64 + j];
    }
    __syncthreads();

    int hg = t >> 5;
    int c0 = (t & 7) * 4, j = (t >> 3) & 3;
    const u64* sXs = (const u64*)Xs;
    const u64* sSd = (const u64*)Sd;
    u64* sMs = (u64*)Ms;

    {
        u64 acc[4][4];
#pragma unroll
        for (int a1 = 0; a1 < 4; a1++)
#pragma unroll
            for (int a2 = 0; a2 < 4; a2++) acc[a1][a2] = 0ull;

        for (int c = 0; c < 32; c++) {
            u64 sv[4];
#pragma unroll
            for (int cc = 0; cc < 4; cc++) sv[cc] = sSd[c * 32 + c0 + cc];
            u64 xv[4];
#pragma unroll
            for (int hh = 0; hh < 4; hh++)
                xv[hh] = sXs[((hg + 8 * hh) * 32 + c) * 4 + j];
#pragma unroll
            for (int hh = 0; hh < 4; hh++)
#pragma unroll
                for (int cc = 0; cc < 4; cc++)
                    acc[hh][cc] = fma2(xv[hh], sv[cc], acc[hh][cc]);
        }
#pragma unroll
        for (int hh = 0; hh < 4; hh++)
#pragma unroll
            for (int cc = 0; cc < 4; cc++)
                sMs[((hg + 8 * hh) * 32 + c0 + cc) * 4 + j] = acc[hh][cc];
    }
    __syncthreads();

    float2* xri = g_xri + (size_t)f * FRAME;
    {
        u64 acc[4][4];
#pragma unroll
        for (int a1 = 0; a1 < 4; a1++)
#pragma unroll
            for (int a2 = 0; a2 < 4; a2++) acc[a1][a2] = 0ull;

        for (int a = 0; a < 32; a++) {
            u64 sv[4];
#pragma unroll
            for (int aa = 0; aa < 4; aa++) sv[aa] = sSd[a * 32 + hg + 8 * aa];
            u64 mv[4];
#pragma unroll
            for (int cc = 0; cc < 4; cc++)
                mv[cc] = sMs[(a * 32 + c0 + cc) * 4 + j];
#pragma unroll
            for (int aa = 0; aa < 4; aa++)
#pragma unroll
                for (int cc = 0; cc < 4; cc++)
                    acc[aa][cc] = fma2(mv[cc], sv[aa], acc[aa][cc]);
        }
#pragma unroll
        for (int aa = 0; aa < 4; aa++)
#pragma unroll
            for (int cc = 0; cc < 4; cc++) {
                int h = hg + 8 * aa, w = c0 + cc;
                float xr, xi;
                unpack2(acc[aa][cc], xr, xi);
                float2 v = rot_posi(make_float2(xr, xi), h + w + 2);
                xri[(size_t)(h * 32 + w) * 64 + p0 + j] = v;
            }
    }
}

// ---------------- K5a: conv C (complex), partial sums to scratch ------------
__global__ void __launch_bounds__(256, 2) conv_c_kernel() {
    int h0 = blockIdx.x * 2, f = blockIdx.y;
    float2* sxri = (float2*)s_raw;              // [4][34][64]
    int t = threadIdx.x;
    const float2* src = g_xri + (size_t)f * FRAME;
    for (int i = t; i < 4 * 34 * 64; i += 256) {
        int rr = i / 2176, rem = i % 2176;
        int wp = rem >> 6, ch = rem & 63;
        int hi = h0 - 1 + rr;
        bool valid = (hi >= 0 && hi < HH && wp >= 1 && wp <= 32);
        sxri[i] = valid ? src[((size_t)hi * 32 + (wp - 1)) * 64 + ch]
                        : make_float2(0.f, 0.f);
    }
    __syncthreads();

    int uo = t & 63, wg = t >> 6, w0 = wg * 8;
    u64 acc0[8], acc1[8];
#pragma unroll
    for (int j = 0; j < 8; j++) { acc0[j] = 0ull; acc1[j] = 0ull; }

    const ulonglong2* sx = (const ulonglong2*)sxri;   // [rr][wp][cp]
    const ulonglong2* wc = (const ulonglong2*)g_Wc4;
    for (int cp = 0; cp < 32; cp++) {
        ulonglong2 wv[9];
#pragma unroll
        for (int k = 0; k < 9; k++)
            wv[k] = __ldg(&wc[(k * 32 + cp) * 64 + uo]);
#pragma unroll
        for (int rr = 0; rr < 4; rr++) {
            const ulonglong2* row = sx + (rr * 34 + w0) * 32;
            ulonglong2 xv[10];
#pragma unroll
            for (int m = 0; m < 10; m++) xv[m] = row[m * 32 + cp];
            if (rr < 3) {
#pragma unroll
                for (int dx = 0; dx < 3; dx++)
#pragma unroll
                    for (int j = 0; j < 8; j++) {
                        acc0[j] = fma2(xv[j + dx].x, wv[rr * 3 + dx].x, acc0[j]);
                        acc0[j] = fma2(xv[j + dx].y, wv[rr * 3 + dx].y, acc0[j]);
                    }
            }
            if (rr > 0) {
#pragma unroll
                for (int dx = 0; dx < 3; dx++)
#pragma unroll
                    for (int j = 0; j < 8; j++) {
                        acc1[j] = fma2(xv[j + dx].x, wv[(rr - 1) * 3 + dx].x, acc1[j]);
                        acc1[j] = fma2(xv[j + dx].y, wv[(rr - 1) * 3 + dx].y, acc1[j]);
                    }
            }
        }
    }
    float* part = (float*)g_Bu;   // scratch reuse (g_Bu dead after fwd_transform)
    size_t base0 = (size_t)f * FRAME + (size_t)h0 * 32 * 64;
    size_t base1 = base0 + 32 * 64;
#pragma unroll
    for (int j = 0; j < 8; j++) {
        float lo, hi;
        unpack2(acc0[j], lo, hi);
        part[base0 + (w0 + j) * 64 + uo] = lo + hi;
        unpack2(acc1[j], lo, hi);
        part[base1 + (w0 + j) * 64 + uo] = lo + hi;
    }
}

// ---------------- K5b: conv D (real, 4-ch fma2) + partial add + GELU --------
__global__ void __launch_bounds__(256, 2) conv_d_kernel(const float* __restrict__ u,
                                                        float* __restrict__ out) {
    int h0 = blockIdx.x * 2, f = blockIdx.y;
    float* su = (float*)s_raw;                  // [4][34][64]
    int t = threadIdx.x;
    const float* u_src = u + (size_t)f * FRAME;
    for (int i = t; i < 4 * 34 * 64; i += 256) {
        int rr = i / 2176, rem = i % 2176;
        int wp = rem >> 6, ch = rem & 63;
        int hi = h0 - 1 + rr;
        bool valid = (hi >= 0 && hi < HH && wp >= 1 && wp <= 32);
        su[i] = valid ? u_src[((size_t)hi * 32 + (wp - 1)) * 64 + ch] : 0.f;
    }
    __syncthreads();

    int uo = t & 63, wg = t >> 6, w0 = wg * 8;
    u64 acc0[8], acc1[8];
#pragma unroll
    for (int j = 0; j < 8; j++) { acc0[j] = 0ull; acc1[j] = 0ull; }

    const ulonglong2* sup = (const ulonglong2*)su;    // [rr][wp][cq], 16 per wp
    const ulonglong2* wd = (const ulonglong2*)g_Wd4;
    for (int cq = 0; cq < 16; cq++) {
        ulonglong2 wv[9];
#pragma unroll
        for (int k = 0; k < 9; k++)
            wv[k] = __ldg(&wd[(k * 16 + cq) * 64 + uo]);
#pragma unroll
        for (int rr = 0; rr < 4; rr++) {
            const ulonglong2* row = sup + (rr * 34 + w0) * 16;
            ulonglong2 uv[10];
#pragma unroll
            for (int m = 0; m < 10; m++) uv[m] = row[m * 16 + cq];
            if (rr < 3) {
#pragma unroll
                for (int dx = 0; dx < 3; dx++)
#pragma unroll
                    for (int j = 0; j < 8; j++) {
                        acc0[j] = fma2(uv[j + dx].x, wv[rr * 3 + dx].x, acc0[j]);
                        acc0[j] = fma2(uv[j + dx].y, wv[rr * 3 + dx].y, acc0[j]);
                    }
            }
            if (rr > 0) {
#pragma unroll
                for (int dx = 0; dx < 3; dx++)
#pragma unroll
                    for (int j = 0; j < 8; j++) {
                        acc1[j] = fma2(uv[j + dx].x, wv[(rr - 1) * 3 + dx].x, acc1[j]);
                        acc1[j] = fma2(uv[j + dx].y, wv[(rr - 1) * 3 + dx].y, acc1[j]);
                    }
            }
        }
    }
    const float* part = (const float*)g_Bu;
    size_t base0 = (size_t)f * FRAME + (size_t)h0 * 32 * 64;
    size_t base1 = base0 + 32 * 64;
#pragma unroll
    for (int j = 0; j < 8; j++) {
        float lo, hi;
        unpack2(acc0[j], lo, hi);
        float x = lo + hi + part[base0 + (w0 + j) * 64 + uo];
        float inner = 0.7978845608028654f * (x + 0.044715f * x * x * x);
        out[base0 + (w0 + j) * 64 + uo] = 0.5f * x * (1.f + tanhf(inner));
        unpack2(acc1[j], lo, hi);
        x = lo + hi + part[base1 + (w0 + j) * 64 + uo];
        inner = 0.7978845608028654f * (x + 0.044715f * x * x * x);
        out[base1 + (w0 + j) * 64 + uo] = 0.5f * x * (1.f + tanhf(inner));
    }
}

// ---------------- launch ----------------------------------------------------
extern "C" void kernel_launch(void* const* d_in, const int* in_sizes, int n_in,
                              void* d_out, int out_size) {
    const float* u        = (const float*)d_in[0];
    const float* x0       = (const float*)d_in[1];
    const float* Lre      = (const float*)d_in[2];
    const float* Lim      = (const float*)d_in[3];
    const float* values   = (const float*)d_in[4];
    const float* log_step = (const float*)d_in[5];
    const float* Br       = (const float*)d_in[6];
    const float* Bi       = (const float*)d_in[7];
    const float* Cr       = (const float*)d_in[8];
    const float* Ci       = (const float*)d_in[9];
    const float* Dk       = (const float*)d_in[10];
    float* out = (float*)d_out;

    static const size_t TSM = (4096 + 4096 + 1024) * sizeof(float2);   // 73728 B
    static const size_t BSM = 4 * 34 * 64 * sizeof(float2);            // 69632 B
    static const size_t CSM = 4 * 34 * 64 * sizeof(float2);            // 69632 B
    static const size_t DSM = 4 * 34 * 64 * sizeof(float);             // 34816 B
    cudaFuncSetAttribute(fwd_transform_kernel, cudaFuncAttributeMaxDynamicSharedMemorySize, (int)TSM);
    cudaFuncSetAttribute(inv_transform_kernel, cudaFuncAttributeMaxDynamicSharedMemorySize, (int)TSM);
    cudaFuncSetAttribute(conv_b_kernel,        cudaFuncAttributeMaxDynamicSharedMemorySize, (int)BSM);
    cudaFuncSetAttribute(conv_c_kernel,        cudaFuncAttributeMaxDynamicSharedMemorySize, (int)CSM);
    cudaFuncSetAttribute(conv_d_kernel,        cudaFuncAttributeMaxDynamicSharedMemorySize, (int)DSM);

    // conv_b is the 4th launch (ncu captures launch #4).
    k_pack_b<<<72, 256>>>(Br, Bi);
    k_pack_c<<<72, 256>>>(Cr, Ci);
    k_pack_d<<<36, 256>>>(Dk);
    conv_b_kernel<<<dim3(16, NFX), 256, BSM>>>(u, x0);
    k_precompute_q<<<1, 1024>>>();
    k_precompute_ab<<<256, 256>>>(Lre, Lim, values, log_step);
    fwd_transform_kernel<<<dim3(16, NFX), 256, TSM>>>();
    scan_kernel<<<2048, 256>>>();
    inv_transform_kernel<<<dim3(16, NF), 256, TSM>>>();
    conv_c_kernel<<<dim3(16, NF), 256, CSM>>>();
    conv_d_kernel<<<dim3(16, NF), 256, DSM>>>(u, out);
    (void)in_sizes; (void)n_in; (void)out_size;
}

// round 12
// speedup vs baseline: 1.0164x; 1.0164x over previous
#include <cuda_runtime.h>
#include <math.h>

// Problem constants
#define HH 32
#define WW 32
#define PP 64
#define UU 64
#define LL 32
#define BB 8
#define NF 256          // L*B frames
#define NFX 264         // + 8 x0 frames
#define FRAME 65536     // 32*32*64 elements per frame-channel block

typedef unsigned long long u64;

// single dynamic-smem symbol shared by all kernels
extern __shared__ char s_raw[];

// ---------------- packed f32x2 helpers --------------------------------------
__device__ __forceinline__ u64 fma2(u64 a, u64 b, u64 c) {
    u64 d;
    asm("fma.rn.f32x2 %0, %1, %2, %3;" : "=l"(d) : "l"(a), "l"(b), "l"(c));
    return d;
}
__device__ __forceinline__ void unpack2(u64 v, float& lo, float& hi) {
    asm("mov.b64 {%0, %1}, %2;" : "=f"(lo), "=f"(hi) : "l"(v));
}

// multiply by (-i)^k
__device__ __forceinline__ float2 rot_negi(float2 x, int k) {
    switch (k & 3) {
        case 0: return x;
        case 1: return make_float2(x.y, -x.x);
        case 2: return make_float2(-x.x, -x.y);
        default: return make_float2(-x.y, x.x);
    }
}
// multiply by i^k
__device__ __forceinline__ float2 rot_posi(float2 x, int k) {
    switch (k & 3) {
        case 0: return x;
        case 1: return make_float2(-x.y, x.x);
        case 2: return make_float2(-x.x, -x.y);
        default: return make_float2(x.y, -x.x);
    }
}

// ---------------- scratch (device globals; no allocation allowed) -------------
__device__ float2 g_Bu[(size_t)NFX * FRAME];   // conv-B output; later reused as
                                               // float scratch for conv-C partials
__device__ float2 g_sp[(size_t)NF * FRAME];    // spectral b_elems -> scan output (in-place)
__device__ float2 g_x0t[(size_t)BB * FRAME];   // B_coeff * transform(B x0)
__device__ float2 g_xri[(size_t)NF * FRAME];   // (Re, Im) of x_sp, interleaved
__device__ float2 g_Abar[FRAME];               // [h][w][p] (== [a][c][p])
__device__ float2 g_Bcoef[FRAME];
__device__ float2 g_Sdup[1024];                // real DST matrix S[m][n], duplicated (s,s)
__device__ float4 g_Wb4[9 * 32 * 64];          // [tap][cp][p]: (Br[2cp],Bi[2cp],Br[2cp+1],Bi[2cp+1])
__device__ float4 g_Wc4[9 * 32 * 64];          // [tap][cp][uo]: (2Cr,-2Ci for ci, then ci+1)
__device__ float4 g_Wd4[9 * 16 * 64];          // [tap][cq][uo]: Dk for 4 consecutive ci

// ---------------- K0: S matrix + A_bar + B_coeff (merged) -------------------
__global__ void k_precompute_qab(const float* __restrict__ Lre,
                                 const float* __restrict__ Lim,
                                 const float* __restrict__ values,
                                 const float* __restrict__ log_step) {
    int idx = blockIdx.x * 256 + threadIdx.x;   // [h][w][p]

    // first 1024 threads also build the DST core matrix S (duplicated)
    if (idx < 1024) {
        int m = idx / 32 + 1, n = idx % 32 + 1;
        double s = sin(M_PI * (double)m * (double)n / 33.0) / sqrt(16.5);
        g_Sdup[idx] = make_float2((float)s, (float)s);
    }

    int p = idx & 63, w = (idx >> 6) & 31, h = idx >> 11;

    float v0 = values[p * 4 + 0], v1 = values[p * 4 + 1];
    float v2 = values[p * 4 + 2], v3 = values[p * 4 + 3];
    float mx = fmaxf(fmaxf(v0, v1), fmaxf(v2, v3));
    float e0 = expf(v0 - mx), e1 = expf(v1 - mx), e2 = expf(v2 - mx), e3 = expf(v3 - mx);
    float inv = 4.f / (e0 + e1 + e2 + e3);
    float xk = e0 * inv, yk = e1 * inv, zk = e2 * inv, wk = e3 * inv;
    float kv0 = (xk + yk - 2.f) * 0.25f;
    float kv1 = (xk + zk - 2.f) * 0.25f;
    float kv2 = (xk + wk - 2.f) * 0.125f;

    double ch = 2.0 * cos(M_PI * (double)(h + 1) / 33.0);
    double cw = 2.0 * cos(M_PI * (double)(w + 1) / 33.0);
    float Dv = kv0 * (float)cw + kv1 * (float)ch + kv2 * (float)(ch * cw) + 1.f;

    float lre = fminf(Lre[p], -1e-4f);
    float lim = Lim[p];
    float st = expf(log_step[p]);

    float tre = lre * Dv, tim = lim * Dv;
    float er = expf(tre * st);
    float Ar = er * cosf(tim * st);
    float Ai = er * sinf(tim * st);
    g_Abar[idx] = make_float2(Ar, Ai);

    float den = tre * tre + tim * tim;
    float br = ((Ar - 1.f) * tre + Ai * tim) / den;
    float bi = (Ai * tre - (Ar - 1.f) * tim) / den;
    g_Bcoef[idx] = make_float2(br, bi);
}

// ---------------- K0c/K0d/K0e: weight packing (ci-pair float4) --------------
__global__ void k_pack_b(const float* __restrict__ Br, const float* __restrict__ Bi) {
    int i = blockIdx.x * 256 + threadIdx.x;     // 0..18431 [tap][cp][p]
    int p = i & 63, cp = (i >> 6) & 31, tap = i >> 11;
    int i0 = (tap * 64 + 2 * cp) * 64 + p;
    g_Wb4[i] = make_float4(Br[i0], Bi[i0], Br[i0 + 64], Bi[i0 + 64]);
}
__global__ void k_pack_c(const float* __restrict__ Cr, const float* __restrict__ Ci) {
    int i = blockIdx.x * 256 + threadIdx.x;     // [tap][cp][uo]
    int uo = i & 63, cp = (i >> 6) & 31, tap = i >> 11;
    int i0 = (tap * 64 + 2 * cp) * 64 + uo;
    g_Wc4[i] = make_float4(2.f * Cr[i0], -2.f * Ci[i0],
                           2.f * Cr[i0 + 64], -2.f * Ci[i0 + 64]);
}
__global__ void k_pack_d(const float* __restrict__ Dk) {
    int i = blockIdx.x * 256 + threadIdx.x;     // 0..9215 [tap][cq][uo]
    int uo = i & 63, cq = (i >> 6) & 15, tap = i >> 10;
    int i0 = (tap * 64 + 4 * cq) * 64 + uo;
    g_Wd4[i] = make_float4(Dk[i0], Dk[i0 + 64], Dk[i0 + 128], Dk[i0 + 192]);
}

// ---------------- K1: conv B (complex, fma2, 2 output rows per block) -------
// block = (row-pair h0, frame f), 256 threads: thread = (p = t&63, wgroup = t>>6)
__global__ void __launch_bounds__(256, 2) conv_b_kernel(const float* __restrict__ u,
                                                        const float* __restrict__ x0) {
    int h0 = blockIdx.x * 2, f = blockIdx.y;
    const float* src = (f < NF) ? (u + (size_t)f * FRAME)
                                : (x0 + (size_t)(f - NF) * FRAME);
    float2* sdup = (float2*)s_raw;              // [4][34][64] duplicated values
    int t = threadIdx.x;
    for (int i = t; i < 4 * 34 * 64; i += 256) {
        int rr = i / 2176, rem = i % 2176;
        int wp = rem >> 6, ch = rem & 63;
        int hi = h0 - 1 + rr;
        float v = 0.f;
        if (hi >= 0 && hi < HH && wp >= 1 && wp <= 32)
            v = src[((size_t)hi * 32 + (wp - 1)) * 64 + ch];
        sdup[i] = make_float2(v, v);
    }
    __syncthreads();

    int p = t & 63, wg = t >> 6, w0 = wg * 8;
    u64 acc0[8], acc1[8];
#pragma unroll
    for (int j = 0; j < 8; j++) { acc0[j] = 0ull; acc1[j] = 0ull; }

    const ulonglong2* sd = (const ulonglong2*)sdup;   // [rr][wp][cp]
    const ulonglong2* wb = (const ulonglong2*)g_Wb4;
    for (int cp = 0; cp < 32; cp++) {
        ulonglong2 wv[9];
#pragma unroll
        for (int k = 0; k < 9; k++)
            wv[k] = __ldg(&wb[(k * 32 + cp) * 64 + p]);
#pragma unroll
        for (int rr = 0; rr < 4; rr++) {
            const ulonglong2* row = sd + (rr * 34 + w0) * 32;
            ulonglong2 xv[10];
#pragma unroll
            for (int m = 0; m < 10; m++) xv[m] = row[m * 32 + cp];
            if (rr < 3) {
#pragma unroll
                for (int dx = 0; dx < 3; dx++)
#pragma unroll
                    for (int j = 0; j < 8; j++) {
                        acc0[j] = fma2(xv[j + dx].x, wv[rr * 3 + dx].x, acc0[j]);
                        acc0[j] = fma2(xv[j + dx].y, wv[rr * 3 + dx].y, acc0[j]);
                    }
            }
            if (rr > 0) {
#pragma unroll
                for (int dx = 0; dx < 3; dx++)
#pragma unroll
                    for (int j = 0; j < 8; j++) {
                        acc1[j] = fma2(xv[j + dx].x, wv[(rr - 1) * 3 + dx].x, acc1[j]);
                        acc1[j] = fma2(xv[j + dx].y, wv[(rr - 1) * 3 + dx].y, acc1[j]);
                    }
            }
        }
    }
    u64* dst0 = (u64*)(g_Bu + (size_t)f * FRAME + (size_t)h0 * 32 * 64);
    u64* dst1 = dst0 + 32 * 64;
#pragma unroll
    for (int j = 0; j < 8; j++) {
        dst0[(w0 + j) * 64 + p] = acc0[j];
        dst1[(w0 + j) * 64 + p] = acc1[j];
    }
}

// ---------------- K2: forward transform (real-S two-sided) + B_coeff --------
// 128 threads (R10 config): hg=t>>4, c0=(r&7)*4, jp=(r>>3)*2; tile 4x4x2
__global__ void fwd_transform_kernel() {
    float2* Xs = (float2*)s_raw;        // 4096
    float2* Ms = Xs + 4096;             // 4096
    float2* Sd = Ms + 4096;             // 1024
    int f = blockIdx.y;
    int p0 = blockIdx.x * 4;
    int t = threadIdx.x;

    for (int i = t; i < 1024; i += 128) Sd[i] = g_Sdup[i];
    const float2* src = g_Bu + (size_t)f * FRAME + p0;
    for (int i = t; i < 4096; i += 128) {
        int j = i & 3, hw = i >> 2;
        int h = hw >> 5, w = hw & 31;
        Xs[i] = rot_negi(src[(size_t)hw * 64 + j], h + w + 2);
    }
    __syncthreads();

    int hg = t >> 4, r = t & 15;
    int c0 = (r & 7) * 4, jp = (r >> 3) * 2;
    const u64* sXs = (const u64*)Xs;
    const u64* sSd = (const u64*)Sd;
    u64* sMs = (u64*)Ms;

    {
        u64 acc[4][4][2];
#pragma unroll
        for (int a1 = 0; a1 < 4; a1++)
#pragma unroll
            for (int a2 = 0; a2 < 4; a2++)
#pragma unroll
                for (int a3 = 0; a3 < 2; a3++) acc[a1][a2][a3] = 0ull;

        for (int w = 0; w < 32; w++) {
            u64 sv[4];
#pragma unroll
            for (int cc = 0; cc < 4; cc++) sv[cc] = sSd[w * 32 + c0 + cc];
            u64 xv[4][2];
#pragma unroll
            for (int hh = 0; hh < 4; hh++)
#pragma unroll
                for (int jj = 0; jj < 2; jj++)
                    xv[hh][jj] = sXs[((hg + 8 * hh) * 32 + w) * 4 + jp + jj];
#pragma unroll
            for (int hh = 0; hh < 4; hh++)
#pragma unroll
                for (int cc = 0; cc < 4; cc++)
#pragma unroll
                    for (int jj = 0; jj < 2; jj++)
                        acc[hh][cc][jj] = fma2(xv[hh][jj], sv[cc], acc[hh][cc][jj]);
        }
#pragma unroll
        for (int hh = 0; hh < 4; hh++)
#pragma unroll
            for (int cc = 0; cc < 4; cc++)
#pragma unroll
                for (int jj = 0; jj < 2; jj++)
                    sMs[((hg + 8 * hh) * 32 + c0 + cc) * 4 + jp + jj] = acc[hh][cc][jj];
    }
    __syncthreads();

    bool isx0 = (f >= NF);
    float2* dst = isx0 ? g_x0t : g_sp;
    size_t base = isx0 ? (size_t)(f - NF) * FRAME : (size_t)f * FRAME;

    {
        u64 acc[4][4][2];
#pragma unroll
        for (int a1 = 0; a1 < 4; a1++)
#pragma unroll
            for (int a2 = 0; a2 < 4; a2++)
#pragma unroll
                for (int a3 = 0; a3 < 2; a3++) acc[a1][a2][a3] = 0ull;

        for (int h = 0; h < 32; h++) {
            u64 sv[4];
#pragma unroll
            for (int aa = 0; aa < 4; aa++) sv[aa] = sSd[h * 32 + hg + 8 * aa];
            u64 mv[4][2];
#pragma unroll
            for (int cc = 0; cc < 4; cc++)
#pragma unroll
                for (int jj = 0; jj < 2; jj++)
                    mv[cc][jj] = sMs[(h * 32 + c0 + cc) * 4 + jp + jj];
#pragma unroll
            for (int aa = 0; aa < 4; aa++)
#pragma unroll
                for (int cc = 0; cc < 4; cc++)
#pragma unroll
                    for (int jj = 0; jj < 2; jj++)
                        acc[aa][cc][jj] = fma2(mv[cc][jj], sv[aa], acc[aa][cc][jj]);
        }
#pragma unroll
        for (int aa = 0; aa < 4; aa++)
#pragma unroll
            for (int cc = 0; cc < 4; cc++)
#pragma unroll
                for (int jj = 0; jj < 2; jj++) {
                    int a = hg + 8 * aa, c = c0 + cc, j = jp + jj;
                    int acp = (a * 32 + c) * 64 + p0 + j;
                    float xr, xi;
                    unpack2(acc[aa][cc][jj], xr, xi);
                    float2 bc = g_Bcoef[acp];
                    dst[base + acp] = make_float2(xr * bc.x - xi * bc.y,
                                                  xr * bc.y + xi * bc.x);
                }
    }
}

// ---------------- K3: linear recurrence over L (vectorized x2, in place) ----
__global__ void scan_kernel() {
    int idx = blockIdx.x * 256 + threadIdx.x;   // 0..262143 = (b, acp-pair)
    int b = idx >> 15;
    int ap = idx & 32767;
    float4 A = ((const float4*)g_Abar)[ap];
    float4 x = ((const float4*)g_x0t)[((size_t)b << 15) + ap];
    float4* sp4 = (float4*)g_sp;
    for (int l = 0; l < LL; l++) {
        size_t off = ((size_t)(l * BB + b) << 15) + ap;
        float4 v = sp4[off];
        float4 nx;
        nx.x = A.x * x.x - A.y * x.y + v.x;
        nx.y = A.x * x.y + A.y * x.x + v.y;
        nx.z = A.z * x.z - A.w * x.w + v.z;
        nx.w = A.z * x.w + A.w * x.z + v.w;
        x = nx;
        sp4[off] = x;
    }
}

// ---------------- K4: inverse transform (real-S two-sided), 128 threads -----
__global__ void inv_transform_kernel() {
    float2* Xs = (float2*)s_raw;
    float2* Ms = Xs + 4096;
    float2* Sd = Ms + 4096;
    int f = blockIdx.y;
    int p0 = blockIdx.x * 4;
    int t = threadIdx.x;

    for (int i = t; i < 1024; i += 128) Sd[i] = g_Sdup[i];
    const float2* src = g_sp + (size_t)f * FRAME + p0;
    for (int i = t; i < 4096; i += 128) {
        int j = i & 3, ac = i >> 2;
        Xs[i] = src[(size_t)ac * 64 + j];
    }
    __syncthreads();

    int hg = t >> 4, r = t & 15;
    int c0 = (r & 7) * 4, jp = (r >> 3) * 2;
    const u64* sXs = (const u64*)Xs;
    const u64* sSd = (const u64*)Sd;
    u64* sMs = (u64*)Ms;

    {
        u64 acc[4][4][2];
#pragma unroll
        for (int a1 = 0; a1 < 4; a1++)
#pragma unroll
            for (int a2 = 0; a2 < 4; a2++)
#pragma unroll
                for (int a3 = 0; a3 < 2; a3++) acc[a1][a2][a3] = 0ull;

        for (int c = 0; c < 32; c++) {
            u64 sv[4];
#pragma unroll
            for (int cc = 0; cc < 4; cc++) sv[cc] = sSd[c * 32 + c0 + cc];
            u64 xv[4][2];
#pragma unroll
            for (int hh = 0; hh < 4; hh++)
#pragma unroll
                for (int jj = 0; jj < 2; jj++)
                    xv[hh][jj] = sXs[((hg + 8 * hh) * 32 + c) * 4 + jp + jj];
#pragma unroll
            for (int hh = 0; hh < 4; hh++)
#pragma unroll
                for (int cc = 0; cc < 4; cc++)
#pragma unroll
                    for (int jj = 0; jj < 2; jj++)
                        acc[hh][cc][jj] = fma2(xv[hh][jj], sv[cc], acc[hh][cc][jj]);
        }
#pragma unroll
        for (int hh = 0; hh < 4; hh++)
#pragma unroll
            for (int cc = 0; cc < 4; cc++)
#pragma unroll
                for (int jj = 0; jj < 2; jj++)
                    sMs[((hg + 8 * hh) * 32 + c0 + cc) * 4 + jp + jj] = acc[hh][cc][jj];
    }
    __syncthreads();

    float2* xri = g_xri + (size_t)f * FRAME;
    {
        u64 acc[4][4][2];
#pragma unroll
        for (int a1 = 0; a1 < 4; a1++)
#pragma unroll
            for (int a2 = 0; a2 < 4; a2++)
#pragma unroll
                for (int a3 = 0; a3 < 2; a3++) acc[a1][a2][a3] = 0ull;

        for (int a = 0; a < 32; a++) {
            u64 sv[4];
#pragma unroll
            for (int aa = 0; aa < 4; aa++) sv[aa] = sSd[a * 32 + hg + 8 * aa];
            u64 mv[4][2];
#pragma unroll
            for (int cc = 0; cc < 4; cc++)
#pragma unroll
                for (int jj = 0; jj < 2; jj++)
                    mv[cc][jj] = sMs[(a * 32 + c0 + cc) * 4 + jp + jj];
#pragma unroll
            for (int aa = 0; aa < 4; aa++)
#pragma unroll
                for (int cc = 0; cc < 4; cc++)
#pragma unroll
                    for (int jj = 0; jj < 2; jj++)
                        acc[aa][cc][jj] = fma2(mv[cc][jj], sv[aa], acc[aa][cc][jj]);
        }
#pragma unroll
        for (int aa = 0; aa < 4; aa++)
#pragma unroll
            for (int cc = 0; cc < 4; cc++)
#pragma unroll
                for (int jj = 0; jj < 2; jj++) {
                    int h = hg + 8 * aa, w = c0 + cc, j = jp + jj;
                    float xr, xi;
                    unpack2(acc[aa][cc][jj], xr, xi);
                    float2 v = rot_posi(make_float2(xr, xi), h + w + 2);
                    xri[(size_t)(h * 32 + w) * 64 + p0 + j] = v;
                }
    }
}

// ---------------- K5a: conv C (complex), partial sums to scratch ------------
__global__ void __launch_bounds__(256, 2) conv_c_kernel() {
    int h0 = blockIdx.x * 2, f = blockIdx.y;
    float2* sxri = (float2*)s_raw;              // [4][34][64]
    int t = threadIdx.x;
    const float2* src = g_xri + (size_t)f * FRAME;
    for (int i = t; i < 4 * 34 * 64; i += 256) {
        int rr = i / 2176, rem = i % 2176;
        int wp = rem >> 6, ch = rem & 63;
        int hi = h0 - 1 + rr;
        bool valid = (hi >= 0 && hi < HH && wp >= 1 && wp <= 32);
        sxri[i] = valid ? src[((size_t)hi * 32 + (wp - 1)) * 64 + ch]
                        : make_float2(0.f, 0.f);
    }
    __syncthreads();

    int uo = t & 63, wg = t >> 6, w0 = wg * 8;
    u64 acc0[8], acc1[8];
#pragma unroll
    for (int j = 0; j < 8; j++) { acc0[j] = 0ull; acc1[j] = 0ull; }

    const ulonglong2* sx = (const ulonglong2*)sxri;   // [rr][wp][cp]
    const ulonglong2* wc = (const ulonglong2*)g_Wc4;
    for (int cp = 0; cp < 32; cp++) {
        ulonglong2 wv[9];
#pragma unroll
        for (int k = 0; k < 9; k++)
            wv[k] = __ldg(&wc[(k * 32 + cp) * 64 + uo]);
#pragma unroll
        for (int rr = 0; rr < 4; rr++) {
            const ulonglong2* row = sx + (rr * 34 + w0) * 32;
            ulonglong2 xv[10];
#pragma unroll
            for (int m = 0; m < 10; m++) xv[m] = row[m * 32 + cp];
            if (rr < 3) {
#pragma unroll
                for (int dx = 0; dx < 3; dx++)
#pragma unroll
                    for (int j = 0; j < 8; j++) {
                        acc0[j] = fma2(xv[j + dx].x, wv[rr * 3 + dx].x, acc0[j]);
                        acc0[j] = fma2(xv[j + dx].y, wv[rr * 3 + dx].y, acc0[j]);
                    }
            }
            if (rr > 0) {
#pragma unroll
                for (int dx = 0; dx < 3; dx++)
#pragma unroll
                    for (int j = 0; j < 8; j++) {
                        acc1[j] = fma2(xv[j + dx].x, wv[(rr - 1) * 3 + dx].x, acc1[j]);
                        acc1[j] = fma2(xv[j + dx].y, wv[(rr - 1) * 3 + dx].y, acc1[j]);
                    }
            }
        }
    }
    float* part = (float*)g_Bu;   // scratch reuse (g_Bu dead after fwd_transform)
    size_t base0 = (size_t)f * FRAME + (size_t)h0 * 32 * 64;
    size_t base1 = base0 + 32 * 64;
#pragma unroll
    for (int j = 0; j < 8; j++) {
        float lo, hi;
        unpack2(acc0[j], lo, hi);
        part[base0 + (w0 + j) * 64 + uo] = lo + hi;
        unpack2(acc1[j], lo, hi);
        part[base1 + (w0 + j) * 64 + uo] = lo + hi;
    }
}

// ---------------- K5b: conv D (real, 4-ch fma2) + partial add + GELU --------
__global__ void __launch_bounds__(256, 2) conv_d_kernel(const float* __restrict__ u,
                                                        float* __restrict__ out) {
    int h0 = blockIdx.x * 2, f = blockIdx.y;
    float* su = (float*)s_raw;                  // [4][34][64]
    int t = threadIdx.x;
    const float* u_src = u + (size_t)f * FRAME;
    for (int i = t; i < 4 * 34 * 64; i += 256) {
        int rr = i / 2176, rem = i % 2176;
        int wp = rem >> 6, ch = rem & 63;
        int hi = h0 - 1 + rr;
        bool valid = (hi >= 0 && hi < HH && wp >= 1 && wp <= 32);
        su[i] = valid ? u_src[((size_t)hi * 32 + (wp - 1)) * 64 + ch] : 0.f;
    }
    __syncthreads();

    int uo = t & 63, wg = t >> 6, w0 = wg * 8;
    u64 acc0[8], acc1[8];
#pragma unroll
    for (int j = 0; j < 8; j++) { acc0[j] = 0ull; acc1[j] = 0ull; }

    const ulonglong2* sup = (const ulonglong2*)su;    // [rr][wp][cq], 16 per wp
    const ulonglong2* wd = (const ulonglong2*)g_Wd4;
    for (int cq = 0; cq < 16; cq++) {
        ulonglong2 wv[9];
#pragma unroll
        for (int k = 0; k < 9; k++)
            wv[k] = __ldg(&wd[(k * 16 + cq) * 64 + uo]);
#pragma unroll
        for (int rr = 0; rr < 4; rr++) {
            const ulonglong2* row = sup + (rr * 34 + w0) * 16;
            ulonglong2 uv[10];
#pragma unroll
            for (int m = 0; m < 10; m++) uv[m] = row[m * 16 + cq];
            if (rr < 3) {
#pragma unroll
                for (int dx = 0; dx < 3; dx++)
#pragma unroll
                    for (int j = 0; j < 8; j++) {
                        acc0[j] = fma2(uv[j + dx].x, wv[rr * 3 + dx].x, acc0[j]);
                        acc0[j] = fma2(uv[j + dx].y, wv[rr * 3 + dx].y, acc0[j]);
                    }
            }
            if (rr > 0) {
#pragma unroll
                for (int dx = 0; dx < 3; dx++)
#pragma unroll
                    for (int j = 0; j < 8; j++) {
                        acc1[j] = fma2(uv[j + dx].x, wv[(rr - 1) * 3 + dx].x, acc1[j]);
                        acc1[j] = fma2(uv[j + dx].y, wv[(rr - 1) * 3 + dx].y, acc1[j]);
                    }
            }
        }
    }
    const float* part = (const float*)g_Bu;
    size_t base0 = (size_t)f * FRAME + (size_t)h0 * 32 * 64;
    size_t base1 = base0 + 32 * 64;
#pragma unroll
    for (int j = 0; j < 8; j++) {
        float lo, hi;
        unpack2(acc0[j], lo, hi);
        float x = lo + hi + part[base0 + (w0 + j) * 64 + uo];
        float inner = 0.7978845608028654f * (x + 0.044715f * x * x * x);
        out[base0 + (w0 + j) * 64 + uo] = 0.5f * x * (1.f + tanhf(inner));
        unpack2(acc1[j], lo, hi);
        x = lo + hi + part[base1 + (w0 + j) * 64 + uo];
        inner = 0.7978845608028654f * (x + 0.044715f * x * x * x);
        out[base1 + (w0 + j) * 64 + uo] = 0.5f * x * (1.f + tanhf(inner));
    }
}

// ---------------- launch ----------------------------------------------------
extern "C" void kernel_launch(void* const* d_in, const int* in_sizes, int n_in,
                              void* d_out, int out_size) {
    const float* u        = (const float*)d_in[0];
    const float* x0       = (const float*)d_in[1];
    const float* Lre      = (const float*)d_in[2];
    const float* Lim      = (const float*)d_in[3];
    const float* values   = (const float*)d_in[4];
    const float* log_step = (const float*)d_in[5];
    const float* Br       = (const float*)d_in[6];
    const float* Bi       = (const float*)d_in[7];
    const float* Cr       = (const float*)d_in[8];
    const float* Ci       = (const float*)d_in[9];
    const float* Dk       = (const float*)d_in[10];
    float* out = (float*)d_out;

    static const size_t TSM = (4096 + 4096 + 1024) * sizeof(float2);   // 73728 B
    static const size_t BSM = 4 * 34 * 64 * sizeof(float2);            // 69632 B
    static const size_t CSM = 4 * 34 * 64 * sizeof(float2);            // 69632 B
    static const size_t DSM = 4 * 34 * 64 * sizeof(float);             // 34816 B
    cudaFuncSetAttribute(fwd_transform_kernel, cudaFuncAttributeMaxDynamicSharedMemorySize, (int)TSM);
    cudaFuncSetAttribute(inv_transform_kernel, cudaFuncAttributeMaxDynamicSharedMemorySize, (int)TSM);
    cudaFuncSetAttribute(conv_b_kernel,        cudaFuncAttributeMaxDynamicSharedMemorySize, (int)BSM);
    cudaFuncSetAttribute(conv_c_kernel,        cudaFuncAttributeMaxDynamicSharedMemorySize, (int)CSM);
    cudaFuncSetAttribute(conv_d_kernel,        cudaFuncAttributeMaxDynamicSharedMemorySize, (int)DSM);

    // fwd_transform is the 4th launch (ncu captures launch #4).
    k_pack_b<<<72, 256>>>(Br, Bi);
    conv_b_kernel<<<dim3(16, NFX), 256, BSM>>>(u, x0);
    k_precompute_qab<<<256, 256>>>(Lre, Lim, values, log_step);
    fwd_transform_kernel<<<dim3(16, NFX), 128, TSM>>>();
    k_pack_c<<<72, 256>>>(Cr, Ci);
    k_pack_d<<<36, 256>>>(Dk);
    scan_kernel<<<1024, 256>>>();
    inv_transform_kernel<<<dim3(16, NF), 128, TSM>>>();
    conv_c_kernel<<<dim3(16, NF), 256, CSM>>>();
    conv_d_kernel<<<dim3(16, NF), 256, DSM>>>(u, out);
    (void)in_sizes; (void)n_in; (void)out_size;
}

// round 13
// speedup vs baseline: 1.1766x; 1.1576x over previous
#include <cuda_runtime.h>
#include <math.h>

// Problem constants
#define HH 32
#define WW 32
#define PP 64
#define UU 64
#define LL 32
#define BB 8
#define NF 256          // L*B frames
#define NFX 264         // + 8 x0 frames
#define FRAME 65536     // 32*32*64 elements per frame-channel block

typedef unsigned long long u64;

// single dynamic-smem symbol shared by all kernels
extern __shared__ char s_raw[];

// ---------------- packed f32x2 helpers --------------------------------------
__device__ __forceinline__ u64 fma2(u64 a, u64 b, u64 c) {
    u64 d;
    asm("fma.rn.f32x2 %0, %1, %2, %3;" : "=l"(d) : "l"(a), "l"(b), "l"(c));
    return d;
}
__device__ __forceinline__ void unpack2(u64 v, float& lo, float& hi) {
    asm("mov.b64 {%0, %1}, %2;" : "=f"(lo), "=f"(hi) : "l"(v));
}

// multiply by (-i)^k
__device__ __forceinline__ float2 rot_negi(float2 x, int k) {
    switch (k & 3) {
        case 0: return x;
        case 1: return make_float2(x.y, -x.x);
        case 2: return make_float2(-x.x, -x.y);
        default: return make_float2(-x.y, x.x);
    }
}
// multiply by i^k
__device__ __forceinline__ float2 rot_posi(float2 x, int k) {
    switch (k & 3) {
        case 0: return x;
        case 1: return make_float2(-x.y, x.x);
        case 2: return make_float2(-x.x, -x.y);
        default: return make_float2(x.y, -x.x);
    }
}

// ---------------- scratch (device globals; no allocation allowed) -------------
__device__ float2 g_Bu[(size_t)NFX * FRAME];   // conv-B output; later reused as
                                               // float scratch for conv-C partials
// Spectral arrays use the TRANSFORM-NATIVE layout:
//   idx = (p>>2)*4096 + (a*32 + c)*4 + (p&3)
__device__ float2 g_sp[(size_t)NF * FRAME];    // spectral b_elems -> scan output (in-place)
__device__ float2 g_x0t[(size_t)BB * FRAME];   // B_coeff * transform(B x0)
__device__ float2 g_xri[(size_t)NF * FRAME];   // (Re, Im) of x_sp, [hw][p] interleaved
__device__ float2 g_Abar[FRAME];               // transform-native layout
__device__ float2 g_Bcoef[FRAME];              // transform-native layout
__device__ float2 g_Sdup[1024];                // real DST matrix S[m][n], duplicated (s,s)
__device__ float4 g_Wb4[9 * 32 * 64];          // [tap][cp][p]
__device__ float4 g_Wc4[9 * 32 * 64];          // [tap][cp][uo]
__device__ float4 g_Wd4[9 * 16 * 64];          // [tap][cq][uo]

// ---------------- K0: S matrix + A_bar + B_coeff (merged) -------------------
__global__ void k_precompute_qab(const float* __restrict__ Lre,
                                 const float* __restrict__ Lim,
                                 const float* __restrict__ values,
                                 const float* __restrict__ log_step) {
    int idx = blockIdx.x * 256 + threadIdx.x;   // enumerates (a, c, p)

    if (idx < 1024) {
        int m = idx / 32 + 1, n = idx % 32 + 1;
        double s = sin(M_PI * (double)m * (double)n / 33.0) / sqrt(16.5);
        g_Sdup[idx] = make_float2((float)s, (float)s);
    }

    int p = idx & 63, w = (idx >> 6) & 31, h = idx >> 11;

    float v0 = values[p * 4 + 0], v1 = values[p * 4 + 1];
    float v2 = values[p * 4 + 2], v3 = values[p * 4 + 3];
    float mx = fmaxf(fmaxf(v0, v1), fmaxf(v2, v3));
    float e0 = expf(v0 - mx), e1 = expf(v1 - mx), e2 = expf(v2 - mx), e3 = expf(v3 - mx);
    float inv = 4.f / (e0 + e1 + e2 + e3);
    float xk = e0 * inv, yk = e1 * inv, zk = e2 * inv, wk = e3 * inv;
    float kv0 = (xk + yk - 2.f) * 0.25f;
    float kv1 = (xk + zk - 2.f) * 0.25f;
    float kv2 = (xk + wk - 2.f) * 0.125f;

    double ch = 2.0 * cos(M_PI * (double)(h + 1) / 33.0);
    double cw = 2.0 * cos(M_PI * (double)(w + 1) / 33.0);
    float Dv = kv0 * (float)cw + kv1 * (float)ch + kv2 * (float)(ch * cw) + 1.f;

    float lre = fminf(Lre[p], -1e-4f);
    float lim = Lim[p];
    float st = expf(log_step[p]);

    float tre = lre * Dv, tim = lim * Dv;
    float er = expf(tre * st);
    float Ar = er * cosf(tim * st);
    float Ai = er * sinf(tim * st);

    // transform-native layout
    int nidx = ((p >> 2) << 12) + ((h * 32 + w) << 2) + (p & 3);
    g_Abar[nidx] = make_float2(Ar, Ai);

    float den = tre * tre + tim * tim;
    float br = ((Ar - 1.f) * tre + Ai * tim) / den;
    float bi = (Ai * tre - (Ar - 1.f) * tim) / den;
    g_Bcoef[nidx] = make_float2(br, bi);
}

// ---------------- weight packing (ci-pair float4) ----------------------------
__global__ void k_pack_b(const float* __restrict__ Br, const float* __restrict__ Bi) {
    int i = blockIdx.x * 256 + threadIdx.x;     // 0..18431 [tap][cp][p]
    int p = i & 63, cp = (i >> 6) & 31, tap = i >> 11;
    int i0 = (tap * 64 + 2 * cp) * 64 + p;
    g_Wb4[i] = make_float4(Br[i0], Bi[i0], Br[i0 + 64], Bi[i0 + 64]);
}
__global__ void k_pack_c(const float* __restrict__ Cr, const float* __restrict__ Ci) {
    int i = blockIdx.x * 256 + threadIdx.x;     // [tap][cp][uo]
    int uo = i & 63, cp = (i >> 6) & 31, tap = i >> 11;
    int i0 = (tap * 64 + 2 * cp) * 64 + uo;
    g_Wc4[i] = make_float4(2.f * Cr[i0], -2.f * Ci[i0],
                           2.f * Cr[i0 + 64], -2.f * Ci[i0 + 64]);
}
__global__ void k_pack_d(const float* __restrict__ Dk) {
    int i = blockIdx.x * 256 + threadIdx.x;     // 0..9215 [tap][cq][uo]
    int uo = i & 63, cq = (i >> 6) & 15, tap = i >> 10;
    int i0 = (tap * 64 + 4 * cq) * 64 + uo;
    g_Wd4[i] = make_float4(Dk[i0], Dk[i0 + 64], Dk[i0 + 128], Dk[i0 + 192]);
}

// ---------------- K1: conv B (complex, fma2, 2 output rows per block) -------
__global__ void __launch_bounds__(256, 2) conv_b_kernel(const float* __restrict__ u,
                                                        const float* __restrict__ x0) {
    int h0 = blockIdx.x * 2, f = blockIdx.y;
    const float* src = (f < NF) ? (u + (size_t)f * FRAME)
                                : (x0 + (size_t)(f - NF) * FRAME);
    float2* sdup = (float2*)s_raw;              // [4][34][64] duplicated values
    int t = threadIdx.x;
    for (int i = t; i < 4 * 34 * 64; i += 256) {
        int rr = i / 2176, rem = i % 2176;
        int wp = rem >> 6, ch = rem & 63;
        int hi = h0 - 1 + rr;
        float v = 0.f;
        if (hi >= 0 && hi < HH && wp >= 1 && wp <= 32)
            v = src[((size_t)hi * 32 + (wp - 1)) * 64 + ch];
        sdup[i] = make_float2(v, v);
    }
    __syncthreads();

    int p = t & 63, wg = t >> 6, w0 = wg * 8;
    u64 acc0[8], acc1[8];
#pragma unroll
    for (int j = 0; j < 8; j++) { acc0[j] = 0ull; acc1[j] = 0ull; }

    const ulonglong2* sd = (const ulonglong2*)sdup;   // [rr][wp][cp]
    const ulonglong2* wb = (const ulonglong2*)g_Wb4;
    for (int cp = 0; cp < 32; cp++) {
        ulonglong2 wv[9];
#pragma unroll
        for (int k = 0; k < 9; k++)
            wv[k] = __ldg(&wb[(k * 32 + cp) * 64 + p]);
#pragma unroll
        for (int rr = 0; rr < 4; rr++) {
            const ulonglong2* row = sd + (rr * 34 + w0) * 32;
            ulonglong2 xv[10];
#pragma unroll
            for (int m = 0; m < 10; m++) xv[m] = row[m * 32 + cp];
            if (rr < 3) {
#pragma unroll
                for (int dx = 0; dx < 3; dx++)
#pragma unroll
                    for (int j = 0; j < 8; j++) {
                        acc0[j] = fma2(xv[j + dx].x, wv[rr * 3 + dx].x, acc0[j]);
                        acc0[j] = fma2(xv[j + dx].y, wv[rr * 3 + dx].y, acc0[j]);
                    }
            }
            if (rr > 0) {
#pragma unroll
                for (int dx = 0; dx < 3; dx++)
#pragma unroll
                    for (int j = 0; j < 8; j++) {
                        acc1[j] = fma2(xv[j + dx].x, wv[(rr - 1) * 3 + dx].x, acc1[j]);
                        acc1[j] = fma2(xv[j + dx].y, wv[(rr - 1) * 3 + dx].y, acc1[j]);
                    }
            }
        }
    }
    u64* dst0 = (u64*)(g_Bu + (size_t)f * FRAME + (size_t)h0 * 32 * 64);
    u64* dst1 = dst0 + 32 * 64;
#pragma unroll
    for (int j = 0; j < 8; j++) {
        dst0[(w0 + j) * 64 + p] = acc0[j];
        dst1[(w0 + j) * 64 + p] = acc1[j];
    }
}

// ---------------- K2: forward transform (conflict-free tiling) ---------------
// 128 threads: warp wg=t>>5, lane: c5=(t&31)>>2, j=t&3.
// Register tile: 8 (h/a) x 4 (c, stride 8). All LDS unit-stride or broadcast.
__global__ void __launch_bounds__(128, 2) fwd_transform_kernel() {
    float2* Xs = (float2*)s_raw;        // [hw][j] 4096
    float2* Ms = Xs + 4096;             // [(h*32+c)][j] 4096
    float2* Sd = Ms + 4096;             // 1024
    int f = blockIdx.y;
    int p0 = blockIdx.x * 4;
    int t = threadIdx.x;

    for (int i = t; i < 1024; i += 128) Sd[i] = g_Sdup[i];
    const float2* src = g_Bu + (size_t)f * FRAME + p0;
    for (int i = t; i < 4096; i += 128) {
        int j = i & 3, hw = i >> 2;
        int h = hw >> 5, w = hw & 31;
        Xs[i] = rot_negi(src[(size_t)hw * 64 + j], h + w + 2);
    }
    __syncthreads();

    int wg = t >> 5;
    int c5 = (t & 31) >> 2, j = t & 3;
    const u64* sXs = (const u64*)Xs;
    const u64* sSd = (const u64*)Sd;
    u64* sMs = (u64*)Ms;

    {   // pass1: M[h][c][j] = sum_w X'[h][w][j] * S[w][c]
        u64 acc[8][4];
#pragma unroll
        for (int a1 = 0; a1 < 8; a1++)
#pragma unroll
            for (int a2 = 0; a2 < 4; a2++) acc[a1][a2] = 0ull;

        for (int w = 0; w < 32; w++) {
            u64 sv[4];
#pragma unroll
            for (int cc = 0; cc < 4; cc++) sv[cc] = sSd[w * 32 + c5 + 8 * cc];
            u64 xv[8];
#pragma unroll
            for (int hh = 0; hh < 8; hh++)
                xv[hh] = sXs[(((wg + 4 * hh) * 32 + w) << 2) + j];
#pragma unroll
            for (int hh = 0; hh < 8; hh++)
#pragma unroll
                for (int cc = 0; cc < 4; cc++)
                    acc[hh][cc] = fma2(xv[hh], sv[cc], acc[hh][cc]);
        }
#pragma unroll
        for (int hh = 0; hh < 8; hh++)
#pragma unroll
            for (int cc = 0; cc < 4; cc++)
                sMs[(((wg + 4 * hh) * 32 + c5 + 8 * cc) << 2) + j] = acc[hh][cc];
    }
    __syncthreads();

    bool isx0 = (f >= NF);
    float2* dst = isx0 ? g_x0t : g_sp;
    size_t base = isx0 ? (size_t)(f - NF) * FRAME : (size_t)f * FRAME;

    {   // pass2: out[a][c][j] = sum_h S[h][a] * M[h][c][j]
        u64 acc[8][4];
#pragma unroll
        for (int a1 = 0; a1 < 8; a1++)
#pragma unroll
            for (int a2 = 0; a2 < 4; a2++) acc[a1][a2] = 0ull;

        for (int h = 0; h < 32; h++) {
            u64 sv[8];
#pragma unroll
            for (int aa = 0; aa < 8; aa++) sv[aa] = sSd[h * 32 + wg + 4 * aa];
            u64 mv[4];
#pragma unroll
            for (int cc = 0; cc < 4; cc++)
                mv[cc] = sMs[((h * 32 + c5 + 8 * cc) << 2) + j];
#pragma unroll
            for (int aa = 0; aa < 8; aa++)
#pragma unroll
                for (int cc = 0; cc < 4; cc++)
                    acc[aa][cc] = fma2(mv[cc], sv[aa], acc[aa][cc]);
        }
        int pbase = p0 * 1024;
#pragma unroll
        for (int aa = 0; aa < 8; aa++)
#pragma unroll
            for (int cc = 0; cc < 4; cc++) {
                int a = wg + 4 * aa, c = c5 + 8 * cc;
                int idx = pbase + ((a * 32 + c) << 2) + j;
                float xr, xi;
                unpack2(acc[aa][cc], xr, xi);
                float2 bc = g_Bcoef[idx];
                dst[base + idx] = make_float2(xr * bc.x - xi * bc.y,
                                              xr * bc.y + xi * bc.x);
            }
    }
}

// ---------------- K3: linear recurrence over L (vectorized x2, in place) ----
__global__ void scan_kernel() {
    int idx = blockIdx.x * 256 + threadIdx.x;   // (b, element-pair)
    int b = idx >> 15;
    int ap = idx & 32767;
    float4 A = ((const float4*)g_Abar)[ap];
    float4 x = ((const float4*)g_x0t)[((size_t)b << 15) + ap];
    float4* sp4 = (float4*)g_sp;
    for (int l = 0; l < LL; l++) {
        size_t off = ((size_t)(l * BB + b) << 15) + ap;
        float4 v = sp4[off];
        float4 nx;
        nx.x = A.x * x.x - A.y * x.y + v.x;
        nx.y = A.x * x.y + A.y * x.x + v.y;
        nx.z = A.z * x.z - A.w * x.w + v.z;
        nx.w = A.z * x.w + A.w * x.z + v.w;
        x = nx;
        sp4[off] = x;
    }
}

// ---------------- K4: inverse transform (conflict-free tiling) ---------------
__global__ void __launch_bounds__(128, 2) inv_transform_kernel() {
    float2* Xs = (float2*)s_raw;        // [ac][j]
    float2* Ms = Xs + 4096;             // [(a*32+w)][j]
    float2* Sd = Ms + 4096;
    int f = blockIdx.y;
    int p0 = blockIdx.x * 4;
    int t = threadIdx.x;

    for (int i = t; i < 1024; i += 128) Sd[i] = g_Sdup[i];
    // g_sp is transform-native: straight contiguous copy
    const float4* src4 = (const float4*)(g_sp + (size_t)f * FRAME + (size_t)p0 * 1024);
    float4* Xs4 = (float4*)Xs;
    for (int i = t; i < 2048; i += 128) Xs4[i] = src4[i];
    __syncthreads();

    int wg = t >> 5;
    int w5 = (t & 31) >> 2, j = t & 3;
    const u64* sXs = (const u64*)Xs;
    const u64* sSd = (const u64*)Sd;
    u64* sMs = (u64*)Ms;

    {   // pass1: Y[a][w][j] = sum_c X[a][c][j] * S[w][c]  (S symmetric)
        u64 acc[8][4];
#pragma unroll
        for (int a1 = 0; a1 < 8; a1++)
#pragma unroll
            for (int a2 = 0; a2 < 4; a2++) acc[a1][a2] = 0ull;

        for (int c = 0; c < 32; c++) {
            u64 sv[4];
#pragma unroll
            for (int wc = 0; wc < 4; wc++) sv[wc] = sSd[c * 32 + w5 + 8 * wc];
            u64 xv[8];
#pragma unroll
            for (int aa = 0; aa < 8; aa++)
                xv[aa] = sXs[(((wg + 4 * aa) * 32 + c) << 2) + j];
#pragma unroll
            for (int aa = 0; aa < 8; aa++)
#pragma unroll
                for (int wc = 0; wc < 4; wc++)
                    acc[aa][wc] = fma2(xv[aa], sv[wc], acc[aa][wc]);
        }
#pragma unroll
        for (int aa = 0; aa < 8; aa++)
#pragma unroll
            for (int wc = 0; wc < 4; wc++)
                sMs[(((wg + 4 * aa) * 32 + w5 + 8 * wc) << 2) + j] = acc[aa][wc];
    }
    __syncthreads();

    float2* xri = g_xri + (size_t)f * FRAME;
    {   // pass2: out[h][w][j] = i^{h+w+2} * sum_a S[h][a] * Y[a][w][j]
        u64 acc[8][4];
#pragma unroll
        for (int a1 = 0; a1 < 8; a1++)
#pragma unroll
            for (int a2 = 0; a2 < 4; a2++) acc[a1][a2] = 0ull;

        for (int a = 0; a < 32; a++) {
            u64 sv[8];
#pragma unroll
            for (int hh = 0; hh < 8; hh++) sv[hh] = sSd[a * 32 + wg + 4 * hh];
            u64 mv[4];
#pragma unroll
            for (int wc = 0; wc < 4; wc++)
                mv[wc] = sMs[((a * 32 + w5 + 8 * wc) << 2) + j];
#pragma unroll
            for (int hh = 0; hh < 8; hh++)
#pragma unroll
                for (int wc = 0; wc < 4; wc++)
                    acc[hh][wc] = fma2(mv[wc], sv[hh], acc[hh][wc]);
        }
#pragma unroll
        for (int hh = 0; hh < 8; hh++)
#pragma unroll
            for (int wc = 0; wc < 4; wc++) {
                int h = wg + 4 * hh, w = w5 + 8 * wc;
                float xr, xi;
                unpack2(acc[hh][wc], xr, xi);
                float2 v = rot_posi(make_float2(xr, xi), h + w + 2);
                xri[(size_t)(h * 32 + w) * 64 + p0 + j] = v;
            }
    }
}

// ---------------- K5a: conv C (complex), partial sums to scratch ------------
__global__ void __launch_bounds__(256, 2) conv_c_kernel() {
    int h0 = blockIdx.x * 2, f = blockIdx.y;
    float2* sxri = (float2*)s_raw;              // [4][34][64]
    int t = threadIdx.x;
    const float2* src = g_xri + (size_t)f * FRAME;
    for (int i = t; i < 4 * 34 * 64; i += 256) {
        int rr = i / 2176, rem = i % 2176;
        int wp = rem >> 6, ch = rem & 63;
        int hi = h0 - 1 + rr;
        bool valid = (hi >= 0 && hi < HH && wp >= 1 && wp <= 32);
        sxri[i] = valid ? src[((size_t)hi * 32 + (wp - 1)) * 64 + ch]
                        : make_float2(0.f, 0.f);
    }
    __syncthreads();

    int uo = t & 63, wg = t >> 6, w0 = wg * 8;
    u64 acc0[8], acc1[8];
#pragma unroll
    for (int j = 0; j < 8; j++) { acc0[j] = 0ull; acc1[j] = 0ull; }

    const ulonglong2* sx = (const ulonglong2*)sxri;   // [rr][wp][cp]
    const ulonglong2* wc = (const ulonglong2*)g_Wc4;
    for (int cp = 0; cp < 32; cp++) {
        ulonglong2 wv[9];
#pragma unroll
        for (int k = 0; k < 9; k++)
            wv[k] = __ldg(&wc[(k * 32 + cp) * 64 + uo]);
#pragma unroll
        for (int rr = 0; rr < 4; rr++) {
            const ulonglong2* row = sx + (rr * 34 + w0) * 32;
            ulonglong2 xv[10];
#pragma unroll
            for (int m = 0; m < 10; m++) xv[m] = row[m * 32 + cp];
            if (rr < 3) {
#pragma unroll
                for (int dx = 0; dx < 3; dx++)
#pragma unroll
                    for (int j = 0; j < 8; j++) {
                        acc0[j] = fma2(xv[j + dx].x, wv[rr * 3 + dx].x, acc0[j]);
                        acc0[j] = fma2(xv[j + dx].y, wv[rr * 3 + dx].y, acc0[j]);
                    }
            }
            if (rr > 0) {
#pragma unroll
                for (int dx = 0; dx < 3; dx++)
#pragma unroll
                    for (int j = 0; j < 8; j++) {
                        acc1[j] = fma2(xv[j + dx].x, wv[(rr - 1) * 3 + dx].x, acc1[j]);
                        acc1[j] = fma2(xv[j + dx].y, wv[(rr - 1) * 3 + dx].y, acc1[j]);
                    }
            }
        }
    }
    float* part = (float*)g_Bu;   // scratch reuse (g_Bu dead after fwd_transform)
    size_t base0 = (size_t)f * FRAME + (size_t)h0 * 32 * 64;
    size_t base1 = base0 + 32 * 64;
#pragma unroll
    for (int j = 0; j < 8; j++) {
        float lo, hi;
        unpack2(acc0[j], lo, hi);
        part[base0 + (w0 + j) * 64 + uo] = lo + hi;
        unpack2(acc1[j], lo, hi);
        part[base1 + (w0 + j) * 64 + uo] = lo + hi;
    }
}

// ---------------- K5b: conv D (real, 4-ch fma2) + partial add + GELU --------
__global__ void __launch_bounds__(256, 2) conv_d_kernel(const float* __restrict__ u,
                                                        float* __restrict__ out) {
    int h0 = blockIdx.x * 2, f = blockIdx.y;
    float* su = (float*)s_raw;                  // [4][34][64]
    int t = threadIdx.x;
    const float* u_src = u + (size_t)f * FRAME;
    for (int i = t; i < 4 * 34 * 64; i += 256) {
        int rr = i / 2176, rem = i % 2176;
        int wp = rem >> 6, ch = rem & 63;
        int hi = h0 - 1 + rr;
        bool valid = (hi >= 0 && hi < HH && wp >= 1 && wp <= 32);
        su[i] = valid ? u_src[((size_t)hi * 32 + (wp - 1)) * 64 + ch] : 0.f;
    }
    __syncthreads();

    int uo = t & 63, wg = t >> 6, w0 = wg * 8;
    u64 acc0[8], acc1[8];
#pragma unroll
    for (int j = 0; j < 8; j++) { acc0[j] = 0ull; acc1[j] = 0ull; }

    const ulonglong2* sup = (const ulonglong2*)su;    // [rr][wp][cq], 16 per wp
    const ulonglong2* wd = (const ulonglong2*)g_Wd4;
    for (int cq = 0; cq < 16; cq++) {
        ulonglong2 wv[9];
#pragma unroll
        for (int k = 0; k < 9; k++)
            wv[k] = __ldg(&wd[(k * 16 + cq) * 64 + uo]);
#pragma unroll
        for (int rr = 0; rr < 4; rr++) {
            const ulonglong2* row = sup + (rr * 34 + w0) * 16;
            ulonglong2 uv[10];
#pragma unroll
            for (int m = 0; m < 10; m++) uv[m] = row[m * 16 + cq];
            if (rr < 3) {
#pragma unroll
                for (int dx = 0; dx < 3; dx++)
#pragma unroll
                    for (int j = 0; j < 8; j++) {
                        acc0[j] = fma2(uv[j + dx].x, wv[rr * 3 + dx].x, acc0[j]);
                        acc0[j] = fma2(uv[j + dx].y, wv[rr * 3 + dx].y, acc0[j]);
                    }
            }
            if (rr > 0) {
#pragma unroll
                for (int dx = 0; dx < 3; dx++)
#pragma unroll
                    for (int j = 0; j < 8; j++) {
                        acc1[j] = fma2(uv[j + dx].x, wv[(rr - 1) * 3 + dx].x, acc1[j]);
                        acc1[j] = fma2(uv[j + dx].y, wv[(rr - 1) * 3 + dx].y, acc1[j]);
                    }
            }
        }
    }
    const float* part = (const float*)g_Bu;
    size_t base0 = (size_t)f * FRAME + (size_t)h0 * 32 * 64;
    size_t base1 = base0 + 32 * 64;
#pragma unroll
    for (int j = 0; j < 8; j++) {
        float lo, hi;
        unpack2(acc0[j], lo, hi);
        float x = lo + hi + part[base0 + (w0 + j) * 64 + uo];
        float inner = 0.7978845608028654f * (x + 0.044715f * x * x * x);
        out[base0 + (w0 + j) * 64 + uo] = 0.5f * x * (1.f + tanhf(inner));
        unpack2(acc1[j], lo, hi);
        x = lo + hi + part[base1 + (w0 + j) * 64 + uo];
        inner = 0.7978845608028654f * (x + 0.044715f * x * x * x);
        out[base1 + (w0 + j) * 64 + uo] = 0.5f * x * (1.f + tanhf(inner));
    }
}

// ---------------- launch ----------------------------------------------------
extern "C" void kernel_launch(void* const* d_in, const int* in_sizes, int n_in,
                              void* d_out, int out_size) {
    const float* u        = (const float*)d_in[0];
    const float* x0       = (const float*)d_in[1];
    const float* Lre      = (const float*)d_in[2];
    const float* Lim      = (const float*)d_in[3];
    const float* values   = (const float*)d_in[4];
    const float* log_step = (const float*)d_in[5];
    const float* Br       = (const float*)d_in[6];
    const float* Bi       = (const float*)d_in[7];
    const float* Cr       = (const float*)d_in[8];
    const float* Ci       = (const float*)d_in[9];
    const float* Dk       = (const float*)d_in[10];
    float* out = (float*)d_out;

    static const size_t TSM = (4096 + 4096 + 1024) * sizeof(float2);   // 73728 B
    static const size_t BSM = 4 * 34 * 64 * sizeof(float2);            // 69632 B
    static const size_t CSM = 4 * 34 * 64 * sizeof(float2);            // 69632 B
    static const size_t DSM = 4 * 34 * 64 * sizeof(float);             // 34816 B
    cudaFuncSetAttribute(fwd_transform_kernel, cudaFuncAttributeMaxDynamicSharedMemorySize, (int)TSM);
    cudaFuncSetAttribute(inv_transform_kernel, cudaFuncAttributeMaxDynamicSharedMemorySize, (int)TSM);
    cudaFuncSetAttribute(conv_b_kernel,        cudaFuncAttributeMaxDynamicSharedMemorySize, (int)BSM);
    cudaFuncSetAttribute(conv_c_kernel,        cudaFuncAttributeMaxDynamicSharedMemorySize, (int)CSM);
    cudaFuncSetAttribute(conv_d_kernel,        cudaFuncAttributeMaxDynamicSharedMemorySize, (int)DSM);

    // fwd_transform is the 4th launch (ncu captures launch #4).
    k_pack_b<<<72, 256>>>(Br, Bi);
    conv_b_kernel<<<dim3(16, NFX), 256, BSM>>>(u, x0);
    k_precompute_qab<<<256, 256>>>(Lre, Lim, values, log_step);
    fwd_transform_kernel<<<dim3(16, NFX), 128, TSM>>>();
    k_pack_c<<<72, 256>>>(Cr, Ci);
    k_pack_d<<<36, 256>>>(Dk);
    scan_kernel<<<1024, 256>>>();
    inv_transform_kernel<<<dim3(16, NF), 128, TSM>>>();
    conv_c_kernel<<<dim3(16, NF), 256, CSM>>>();
    conv_d_kernel<<<dim3(16, NF), 256, DSM>>>(u, out);
    (void)in_sizes; (void)n_in; (void)out_size;
}

// round 14
// speedup vs baseline: 1.2516x; 1.0638x over previous
#include <cuda_runtime.h>
#include <math.h>

// Problem constants
#define HH 32
#define WW 32
#define PP 64
#define UU 64
#define LL 32
#define BB 8
#define NF 256          // L*B frames
#define NFX 264         // + 8 x0 frames
#define FRAME 65536     // 32*32*64 elements per frame-channel block

typedef unsigned long long u64;

// single dynamic-smem symbol shared by all kernels
extern __shared__ char s_raw[];

// ---------------- packed f32x2 helpers --------------------------------------
__device__ __forceinline__ u64 fma2(u64 a, u64 b, u64 c) {
    u64 d;
    asm("fma.rn.f32x2 %0, %1, %2, %3;" : "=l"(d) : "l"(a), "l"(b), "l"(c));
    return d;
}
__device__ __forceinline__ void unpack2(u64 v, float& lo, float& hi) {
    asm("mov.b64 {%0, %1}, %2;" : "=f"(lo), "=f"(hi) : "l"(v));
}

// multiply by (-i)^k
__device__ __forceinline__ float2 rot_negi(float2 x, int k) {
    switch (k & 3) {
        case 0: return x;
        case 1: return make_float2(x.y, -x.x);
        case 2: return make_float2(-x.x, -x.y);
        default: return make_float2(-x.y, x.x);
    }
}
// multiply by i^k
__device__ __forceinline__ float2 rot_posi(float2 x, int k) {
    switch (k & 3) {
        case 0: return x;
        case 1: return make_float2(-x.y, x.x);
        case 2: return make_float2(-x.x, -x.y);
        default: return make_float2(x.y, -x.x);
    }
}

// ---------------- scratch (device globals; no allocation allowed) -------------
__device__ float2 g_Bu[(size_t)NFX * FRAME];   // conv-B output
// Spectral arrays use the TRANSFORM-NATIVE layout:
//   idx = (p>>2)*4096 + (a*32 + c)*4 + (p&3)
__device__ float2 g_sp[(size_t)NF * FRAME];    // spectral b_elems -> scan output (in-place)
__device__ float2 g_x0t[(size_t)BB * FRAME];   // B_coeff * transform(B x0)
__device__ float2 g_xri[(size_t)NF * FRAME];   // (Re, Im) of x_sp, [hw][p] interleaved
__device__ float2 g_Abar[FRAME];               // transform-native layout
__device__ float2 g_Bcoef[FRAME];              // transform-native layout
__device__ float2 g_Sdup[1024];                // real DST matrix S[m][n], duplicated (s,s)
__device__ float4 g_Wb4[9 * 32 * 64];          // [tap][cp][p]
__device__ float4 g_Wc4[9 * 32 * 64];          // [tap][cp][uo]
__device__ float4 g_Wd4[9 * 16 * 64];          // [tap][cq][uo]

// ---------------- K0: S matrix + A_bar + B_coeff (merged) -------------------
__global__ void k_precompute_qab(const float* __restrict__ Lre,
                                 const float* __restrict__ Lim,
                                 const float* __restrict__ values,
                                 const float* __restrict__ log_step) {
    int idx = blockIdx.x * 256 + threadIdx.x;   // enumerates (a, c, p)

    if (idx < 1024) {
        int m = idx / 32 + 1, n = idx % 32 + 1;
        double s = sin(M_PI * (double)m * (double)n / 33.0) / sqrt(16.5);
        g_Sdup[idx] = make_float2((float)s, (float)s);
    }

    int p = idx & 63, w = (idx >> 6) & 31, h = idx >> 11;

    float v0 = values[p * 4 + 0], v1 = values[p * 4 + 1];
    float v2 = values[p * 4 + 2], v3 = values[p * 4 + 3];
    float mx = fmaxf(fmaxf(v0, v1), fmaxf(v2, v3));
    float e0 = expf(v0 - mx), e1 = expf(v1 - mx), e2 = expf(v2 - mx), e3 = expf(v3 - mx);
    float inv = 4.f / (e0 + e1 + e2 + e3);
    float xk = e0 * inv, yk = e1 * inv, zk = e2 * inv, wk = e3 * inv;
    float kv0 = (xk + yk - 2.f) * 0.25f;
    float kv1 = (xk + zk - 2.f) * 0.25f;
    float kv2 = (xk + wk - 2.f) * 0.125f;

    double ch = 2.0 * cos(M_PI * (double)(h + 1) / 33.0);
    double cw = 2.0 * cos(M_PI * (double)(w + 1) / 33.0);
    float Dv = kv0 * (float)cw + kv1 * (float)ch + kv2 * (float)(ch * cw) + 1.f;

    float lre = fminf(Lre[p], -1e-4f);
    float lim = Lim[p];
    float st = expf(log_step[p]);

    float tre = lre * Dv, tim = lim * Dv;
    float er = expf(tre * st);
    float Ar = er * cosf(tim * st);
    float Ai = er * sinf(tim * st);

    int nidx = ((p >> 2) << 12) + ((h * 32 + w) << 2) + (p & 3);
    g_Abar[nidx] = make_float2(Ar, Ai);

    float den = tre * tre + tim * tim;
    float br = ((Ar - 1.f) * tre + Ai * tim) / den;
    float bi = (Ai * tre - (Ar - 1.f) * tim) / den;
    g_Bcoef[nidx] = make_float2(br, bi);
}

// ---------------- weight packing (ci-pair float4) ----------------------------
__global__ void k_pack_b(const float* __restrict__ Br, const float* __restrict__ Bi) {
    int i = blockIdx.x * 256 + threadIdx.x;     // 0..18431 [tap][cp][p]
    int p = i & 63, cp = (i >> 6) & 31, tap = i >> 11;
    int i0 = (tap * 64 + 2 * cp) * 64 + p;
    g_Wb4[i] = make_float4(Br[i0], Bi[i0], Br[i0 + 64], Bi[i0 + 64]);
}
__global__ void k_pack_c(const float* __restrict__ Cr, const float* __restrict__ Ci) {
    int i = blockIdx.x * 256 + threadIdx.x;     // [tap][cp][uo]
    int uo = i & 63, cp = (i >> 6) & 31, tap = i >> 11;
    int i0 = (tap * 64 + 2 * cp) * 64 + uo;
    g_Wc4[i] = make_float4(2.f * Cr[i0], -2.f * Ci[i0],
                           2.f * Cr[i0 + 64], -2.f * Ci[i0 + 64]);
}
__global__ void k_pack_d(const float* __restrict__ Dk) {
    int i = blockIdx.x * 256 + threadIdx.x;     // 0..9215 [tap][cq][uo]
    int uo = i & 63, cq = (i >> 6) & 15, tap = i >> 10;
    int i0 = (tap * 64 + 4 * cq) * 64 + uo;
    g_Wd4[i] = make_float4(Dk[i0], Dk[i0 + 64], Dk[i0 + 128], Dk[i0 + 192]);
}

// ---------------- K1: conv B (complex, fma2, 2 output rows per block) -------
__global__ void __launch_bounds__(256, 2) conv_b_kernel(const float* __restrict__ u,
                                                        const float* __restrict__ x0) {
    int h0 = blockIdx.x * 2, f = blockIdx.y;
    const float* src = (f < NF) ? (u + (size_t)f * FRAME)
                                : (x0 + (size_t)(f - NF) * FRAME);
    float2* sdup = (float2*)s_raw;              // [4][34][64] duplicated values
    int t = threadIdx.x;
    for (int i = t; i < 4 * 34 * 64; i += 256) {
        int rr = i / 2176, rem = i % 2176;
        int wp = rem >> 6, ch = rem & 63;
        int hi = h0 - 1 + rr;
        float v = 0.f;
        if (hi >= 0 && hi < HH && wp >= 1 && wp <= 32)
            v = src[((size_t)hi * 32 + (wp - 1)) * 64 + ch];
        sdup[i] = make_float2(v, v);
    }
    __syncthreads();

    int p = t & 63, wg = t >> 6, w0 = wg * 8;
    u64 acc0[8], acc1[8];
#pragma unroll
    for (int j = 0; j < 8; j++) { acc0[j] = 0ull; acc1[j] = 0ull; }

    const ulonglong2* sd = (const ulonglong2*)sdup;   // [rr][wp][cp]
    const ulonglong2* wb = (const ulonglong2*)g_Wb4;
    for (int cp = 0; cp < 32; cp++) {
        ulonglong2 wv[9];
#pragma unroll
        for (int k = 0; k < 9; k++)
            wv[k] = __ldg(&wb[(k * 32 + cp) * 64 + p]);
#pragma unroll
        for (int rr = 0; rr < 4; rr++) {
            const ulonglong2* row = sd + (rr * 34 + w0) * 32;
            ulonglong2 xv[10];
#pragma unroll
            for (int m = 0; m < 10; m++) xv[m] = row[m * 32 + cp];
            if (rr < 3) {
#pragma unroll
                for (int dx = 0; dx < 3; dx++)
#pragma unroll
                    for (int j = 0; j < 8; j++) {
                        acc0[j] = fma2(xv[j + dx].x, wv[rr * 3 + dx].x, acc0[j]);
                        acc0[j] = fma2(xv[j + dx].y, wv[rr * 3 + dx].y, acc0[j]);
                    }
            }
            if (rr > 0) {
#pragma unroll
                for (int dx = 0; dx < 3; dx++)
#pragma unroll
                    for (int j = 0; j < 8; j++) {
                        acc1[j] = fma2(xv[j + dx].x, wv[(rr - 1) * 3 + dx].x, acc1[j]);
                        acc1[j] = fma2(xv[j + dx].y, wv[(rr - 1) * 3 + dx].y, acc1[j]);
                    }
            }
        }
    }
    u64* dst0 = (u64*)(g_Bu + (size_t)f * FRAME + (size_t)h0 * 32 * 64);
    u64* dst1 = dst0 + 32 * 64;
#pragma unroll
    for (int j = 0; j < 8; j++) {
        dst0[(w0 + j) * 64 + p] = acc0[j];
        dst1[(w0 + j) * 64 + p] = acc1[j];
    }
}

// ---------------- K2: forward transform (conflict-free tiling) ---------------
__global__ void __launch_bounds__(128, 2) fwd_transform_kernel() {
    float2* Xs = (float2*)s_raw;        // [hw][j] 4096
    float2* Ms = Xs + 4096;             // [(h*32+c)][j] 4096
    float2* Sd = Ms + 4096;             // 1024
    int f = blockIdx.y;
    int p0 = blockIdx.x * 4;
    int t = threadIdx.x;

    for (int i = t; i < 1024; i += 128) Sd[i] = g_Sdup[i];
    // vectorized fill: one 16B load = 2 consecutive j (same rotation factor)
    const ulonglong2* src2 = (const ulonglong2*)(g_Bu + (size_t)f * FRAME + p0);
    ulonglong2* Xs2 = (ulonglong2*)Xs;
    for (int i = t; i < 2048; i += 128) {
        int j2 = i & 1, hw = i >> 1;
        int h = hw >> 5, w = hw & 31;
        ulonglong2 v = src2[hw * 32 + j2];
        float2 a = ((float2*)&v)[0], b = ((float2*)&v)[1];
        int k = h + w + 2;
        a = rot_negi(a, k);
        b = rot_negi(b, k);
        ulonglong2 o;
        ((float2*)&o)[0] = a;
        ((float2*)&o)[1] = b;
        Xs2[i] = o;
    }
    __syncthreads();

    int wg = t >> 5;
    int c5 = (t & 31) >> 2, j = t & 3;
    const u64* sXs = (const u64*)Xs;
    const u64* sSd = (const u64*)Sd;
    u64* sMs = (u64*)Ms;

    {   // pass1: M[h][c][j] = sum_w X'[h][w][j] * S[w][c]
        u64 acc[8][4];
#pragma unroll
        for (int a1 = 0; a1 < 8; a1++)
#pragma unroll
            for (int a2 = 0; a2 < 4; a2++) acc[a1][a2] = 0ull;

        for (int w = 0; w < 32; w++) {
            u64 sv[4];
#pragma unroll
            for (int cc = 0; cc < 4; cc++) sv[cc] = sSd[w * 32 + c5 + 8 * cc];
            u64 xv[8];
#pragma unroll
            for (int hh = 0; hh < 8; hh++)
                xv[hh] = sXs[(((wg + 4 * hh) * 32 + w) << 2) + j];
#pragma unroll
            for (int hh = 0; hh < 8; hh++)
#pragma unroll
                for (int cc = 0; cc < 4; cc++)
                    acc[hh][cc] = fma2(xv[hh], sv[cc], acc[hh][cc]);
        }
#pragma unroll
        for (int hh = 0; hh < 8; hh++)
#pragma unroll
            for (int cc = 0; cc < 4; cc++)
                sMs[(((wg + 4 * hh) * 32 + c5 + 8 * cc) << 2) + j] = acc[hh][cc];
    }
    __syncthreads();

    bool isx0 = (f >= NF);
    float2* dst = isx0 ? g_x0t : g_sp;
    size_t base = isx0 ? (size_t)(f - NF) * FRAME : (size_t)f * FRAME;

    {   // pass2: out[a][c][j] = sum_h S[h][a] * M[h][c][j]
        u64 acc[8][4];
#pragma unroll
        for (int a1 = 0; a1 < 8; a1++)
#pragma unroll
            for (int a2 = 0; a2 < 4; a2++) acc[a1][a2] = 0ull;

        for (int h = 0; h < 32; h++) {
            u64 sv[8];
#pragma unroll
            for (int aa = 0; aa < 8; aa++) sv[aa] = sSd[h * 32 + wg + 4 * aa];
            u64 mv[4];
#pragma unroll
            for (int cc = 0; cc < 4; cc++)
                mv[cc] = sMs[((h * 32 + c5 + 8 * cc) << 2) + j];
#pragma unroll
            for (int aa = 0; aa < 8; aa++)
#pragma unroll
                for (int cc = 0; cc < 4; cc++)
                    acc[aa][cc] = fma2(mv[cc], sv[aa], acc[aa][cc]);
        }
        int pbase = p0 * 1024;
#pragma unroll
        for (int aa = 0; aa < 8; aa++)
#pragma unroll
            for (int cc = 0; cc < 4; cc++) {
                int a = wg + 4 * aa, c = c5 + 8 * cc;
                int idx = pbase + ((a * 32 + c) << 2) + j;
                float xr, xi;
                unpack2(acc[aa][cc], xr, xi);
                float2 bc = g_Bcoef[idx];
                dst[base + idx] = make_float2(xr * bc.x - xi * bc.y,
                                              xr * bc.y + xi * bc.x);
            }
    }
}

// ---------------- K3: linear recurrence over L (vectorized x2, in place) ----
__global__ void scan_kernel() {
    int idx = blockIdx.x * 256 + threadIdx.x;   // (b, element-pair)
    int b = idx >> 15;
    int ap = idx & 32767;
    float4 A = ((const float4*)g_Abar)[ap];
    float4 x = ((const float4*)g_x0t)[((size_t)b << 15) + ap];
    float4* sp4 = (float4*)g_sp;
    for (int l = 0; l < LL; l++) {
        size_t off = ((size_t)(l * BB + b) << 15) + ap;
        float4 v = sp4[off];
        float4 nx;
        nx.x = A.x * x.x - A.y * x.y + v.x;
        nx.y = A.x * x.y + A.y * x.x + v.y;
        nx.z = A.z * x.z - A.w * x.w + v.z;
        nx.w = A.z * x.w + A.w * x.z + v.w;
        x = nx;
        sp4[off] = x;
    }
}

// ---------------- K4: inverse transform (conflict-free tiling) ---------------
__global__ void __launch_bounds__(128, 2) inv_transform_kernel() {
    float2* Xs = (float2*)s_raw;        // [ac][j]
    float2* Ms = Xs + 4096;             // [(a*32+w)][j]
    float2* Sd = Ms + 4096;
    int f = blockIdx.y;
    int p0 = blockIdx.x * 4;
    int t = threadIdx.x;

    for (int i = t; i < 1024; i += 128) Sd[i] = g_Sdup[i];
    const float4* src4 = (const float4*)(g_sp + (size_t)f * FRAME + (size_t)p0 * 1024);
    float4* Xs4 = (float4*)Xs;
    for (int i = t; i < 2048; i += 128) Xs4[i] = src4[i];
    __syncthreads();

    int wg = t >> 5;
    int w5 = (t & 31) >> 2, j = t & 3;
    const u64* sXs = (const u64*)Xs;
    const u64* sSd = (const u64*)Sd;
    u64* sMs = (u64*)Ms;

    {   // pass1: Y[a][w][j] = sum_c X[a][c][j] * S[w][c]
        u64 acc[8][4];
#pragma unroll
        for (int a1 = 0; a1 < 8; a1++)
#pragma unroll
            for (int a2 = 0; a2 < 4; a2++) acc[a1][a2] = 0ull;

        for (int c = 0; c < 32; c++) {
            u64 sv[4];
#pragma unroll
            for (int wc = 0; wc < 4; wc++) sv[wc] = sSd[c * 32 + w5 + 8 * wc];
            u64 xv[8];
#pragma unroll
            for (int aa = 0; aa < 8; aa++)
                xv[aa] = sXs[(((wg + 4 * aa) * 32 + c) << 2) + j];
#pragma unroll
            for (int aa = 0; aa < 8; aa++)
#pragma unroll
                for (int wc = 0; wc < 4; wc++)
                    acc[aa][wc] = fma2(xv[aa], sv[wc], acc[aa][wc]);
        }
#pragma unroll
        for (int aa = 0; aa < 8; aa++)
#pragma unroll
            for (int wc = 0; wc < 4; wc++)
                sMs[(((wg + 4 * aa) * 32 + w5 + 8 * wc) << 2) + j] = acc[aa][wc];
    }
    __syncthreads();

    float2* xri = g_xri + (size_t)f * FRAME;
    {   // pass2: out[h][w][j] = i^{h+w+2} * sum_a S[h][a] * Y[a][w][j]
        u64 acc[8][4];
#pragma unroll
        for (int a1 = 0; a1 < 8; a1++)
#pragma unroll
            for (int a2 = 0; a2 < 4; a2++) acc[a1][a2] = 0ull;

        for (int a = 0; a < 32; a++) {
            u64 sv[8];
#pragma unroll
            for (int hh = 0; hh < 8; hh++) sv[hh] = sSd[a * 32 + wg + 4 * hh];
            u64 mv[4];
#pragma unroll
            for (int wc = 0; wc < 4; wc++)
                mv[wc] = sMs[((a * 32 + w5 + 8 * wc) << 2) + j];
#pragma unroll
            for (int hh = 0; hh < 8; hh++)
#pragma unroll
                for (int wc = 0; wc < 4; wc++)
                    acc[hh][wc] = fma2(mv[wc], sv[hh], acc[hh][wc]);
        }
#pragma unroll
        for (int hh = 0; hh < 8; hh++)
#pragma unroll
            for (int wc = 0; wc < 4; wc++) {
                int h = wg + 4 * hh, w = w5 + 8 * wc;
                float xr, xi;
                unpack2(acc[hh][wc], xr, xi);
                float2 v = rot_posi(make_float2(xr, xi), h + w + 2);
                xri[(size_t)(h * 32 + w) * 64 + p0 + j] = v;
            }
    }
}

// ---------------- K5: conv C then conv D (sequential phases) + GELU ---------
// Phase C: complex conv from g_xri halo; phase D: real conv from u halo
// (same smem region, reused after a sync). One shared accumulator set.
__global__ void __launch_bounds__(256, 2) conv_cd_kernel(const float* __restrict__ u,
                                                         float* __restrict__ out) {
    int h0 = blockIdx.x * 2, f = blockIdx.y;
    int t = threadIdx.x;
    int uo = t & 63, wg = t >> 6, w0 = wg * 8;

    u64 acc0[8], acc1[8];
#pragma unroll
    for (int j = 0; j < 8; j++) { acc0[j] = 0ull; acc1[j] = 0ull; }

    // ---- Phase C ----
    {
        float2* sxri = (float2*)s_raw;          // [4][34][64]
        const float2* src = g_xri + (size_t)f * FRAME;
        for (int i = t; i < 4 * 34 * 64; i += 256) {
            int rr = i / 2176, rem = i % 2176;
            int wp = rem >> 6, ch = rem & 63;
            int hi = h0 - 1 + rr;
            bool valid = (hi >= 0 && hi < HH && wp >= 1 && wp <= 32);
            sxri[i] = valid ? src[((size_t)hi * 32 + (wp - 1)) * 64 + ch]
                            : make_float2(0.f, 0.f);
        }
        __syncthreads();

        const ulonglong2* sx = (const ulonglong2*)sxri;   // [rr][wp][cp]
        const ulonglong2* wc = (const ulonglong2*)g_Wc4;
        for (int cp = 0; cp < 32; cp++) {
            ulonglong2 wv[9];
#pragma unroll
            for (int k = 0; k < 9; k++)
                wv[k] = __ldg(&wc[(k * 32 + cp) * 64 + uo]);
#pragma unroll
            for (int rr = 0; rr < 4; rr++) {
                const ulonglong2* row = sx + (rr * 34 + w0) * 32;
                ulonglong2 xv[10];
#pragma unroll
                for (int m = 0; m < 10; m++) xv[m] = row[m * 32 + cp];
                if (rr < 3) {
#pragma unroll
                    for (int dx = 0; dx < 3; dx++)
#pragma unroll
                        for (int j = 0; j < 8; j++) {
                            acc0[j] = fma2(xv[j + dx].x, wv[rr * 3 + dx].x, acc0[j]);
                            acc0[j] = fma2(xv[j + dx].y, wv[rr * 3 + dx].y, acc0[j]);
                        }
                }
                if (rr > 0) {
#pragma unroll
                    for (int dx = 0; dx < 3; dx++)
#pragma unroll
                        for (int j = 0; j < 8; j++) {
                            acc1[j] = fma2(xv[j + dx].x, wv[(rr - 1) * 3 + dx].x, acc1[j]);
                            acc1[j] = fma2(xv[j + dx].y, wv[(rr - 1) * 3 + dx].y, acc1[j]);
                        }
                }
            }
        }
    }
    __syncthreads();   // all reads of sxri done before overwrite

    // ---- Phase D ----
    {
        float* su = (float*)s_raw;              // [4][34][64] (reuses same smem)
        const float* u_src = u + (size_t)f * FRAME;
        for (int i = t; i < 4 * 34 * 64; i += 256) {
            int rr = i / 2176, rem = i % 2176;
            int wp = rem >> 6, ch = rem & 63;
            int hi = h0 - 1 + rr;
            bool valid = (hi >= 0 && hi < HH && wp >= 1 && wp <= 32);
            su[i] = valid ? u_src[((size_t)hi * 32 + (wp - 1)) * 64 + ch] : 0.f;
        }
        __syncthreads();

        const ulonglong2* sup = (const ulonglong2*)su;    // [rr][wp][cq]
        const ulonglong2* wd = (const ulonglong2*)g_Wd4;
        for (int cq = 0; cq < 16; cq++) {
            ulonglong2 wv[9];
#pragma unroll
            for (int k = 0; k < 9; k++)
                wv[k] = __ldg(&wd[(k * 16 + cq) * 64 + uo]);
#pragma unroll
            for (int rr = 0; rr < 4; rr++) {
                const ulonglong2* row = sup + (rr * 34 + w0) * 16;
                ulonglong2 uv[10];
#pragma unroll
                for (int m = 0; m < 10; m++) uv[m] = row[m * 16 + cq];
                if (rr < 3) {
#pragma unroll
                    for (int dx = 0; dx < 3; dx++)
#pragma unroll
                        for (int j = 0; j < 8; j++) {
                            acc0[j] = fma2(uv[j + dx].x, wv[rr * 3 + dx].x, acc0[j]);
                            acc0[j] = fma2(uv[j + dx].y, wv[rr * 3 + dx].y, acc0[j]);
                        }
                }
                if (rr > 0) {
#pragma unroll
                    for (int dx = 0; dx < 3; dx++)
#pragma unroll
                        for (int j = 0; j < 8; j++) {
                            acc1[j] = fma2(uv[j + dx].x, wv[(rr - 1) * 3 + dx].x, acc1[j]);
                            acc1[j] = fma2(uv[j + dx].y, wv[(rr - 1) * 3 + dx].y, acc1[j]);
                        }
                }
            }
        }
    }

    size_t base0 = (size_t)f * FRAME + (size_t)h0 * 32 * 64;
    size_t base1 = base0 + 32 * 64;
#pragma unroll
    for (int j = 0; j < 8; j++) {
        float lo, hi;
        unpack2(acc0[j], lo, hi);
        float x = lo + hi;
        float inner = 0.7978845608028654f * (x + 0.044715f * x * x * x);
        out[base0 + (w0 + j) * 64 + uo] = 0.5f * x * (1.f + tanhf(inner));
        unpack2(acc1[j], lo, hi);
        x = lo + hi;
        inner = 0.7978845608028654f * (x + 0.044715f * x * x * x);
        out[base1 + (w0 + j) * 64 + uo] = 0.5f * x * (1.f + tanhf(inner));
    }
}

// ---------------- launch ----------------------------------------------------
extern "C" void kernel_launch(void* const* d_in, const int* in_sizes, int n_in,
                              void* d_out, int out_size) {
    const float* u        = (const float*)d_in[0];
    const float* x0       = (const float*)d_in[1];
    const float* Lre      = (const float*)d_in[2];
    const float* Lim      = (const float*)d_in[3];
    const float* values   = (const float*)d_in[4];
    const float* log_step = (const float*)d_in[5];
    const float* Br       = (const float*)d_in[6];
    const float* Bi       = (const float*)d_in[7];
    const float* Cr       = (const float*)d_in[8];
    const float* Ci       = (const float*)d_in[9];
    const float* Dk       = (const float*)d_in[10];
    float* out = (float*)d_out;

    static const size_t TSM = (4096 + 4096 + 1024) * sizeof(float2);   // 73728 B
    static const size_t BSM = 4 * 34 * 64 * sizeof(float2);            // 69632 B
    static const size_t CSM = 4 * 34 * 64 * sizeof(float2);            // 69632 B
    cudaFuncSetAttribute(fwd_transform_kernel, cudaFuncAttributeMaxDynamicSharedMemorySize, (int)TSM);
    cudaFuncSetAttribute(inv_transform_kernel, cudaFuncAttributeMaxDynamicSharedMemorySize, (int)TSM);
    cudaFuncSetAttribute(conv_b_kernel,        cudaFuncAttributeMaxDynamicSharedMemorySize, (int)BSM);
    cudaFuncSetAttribute(conv_cd_kernel,       cudaFuncAttributeMaxDynamicSharedMemorySize, (int)CSM);

    // fwd_transform is the 4th launch (ncu captures launch #4).
    k_pack_b<<<72, 256>>>(Br, Bi);
    conv_b_kernel<<<dim3(16, NFX), 256, BSM>>>(u, x0);
    k_precompute_qab<<<256, 256>>>(Lre, Lim, values, log_step);
    fwd_transform_kernel<<<dim3(16, NFX), 128, TSM>>>();
    k_pack_c<<<72, 256>>>(Cr, Ci);
    k_pack_d<<<36, 256>>>(Dk);
    scan_kernel<<<1024, 256>>>();
    inv_transform_kernel<<<dim3(16, NF), 128, TSM>>>();
    conv_cd_kernel<<<dim3(16, NF), 256, CSM>>>(u, out);
    (void)in_sizes; (void)n_in; (void)out_size;
}

// round 15
// speedup vs baseline: 1.2952x; 1.0348x over previous
#include <cuda_runtime.h>
#include <math.h>

// Problem constants
#define HH 32
#define WW 32
#define PP 64
#define UU 64
#define LL 32
#define BB 8
#define NF 256          // L*B frames
#define NFX 264         // + 8 x0 frames
#define FRAME 65536     // 32*32*64 elements per frame-channel block

typedef unsigned long long u64;

// single dynamic-smem symbol shared by all kernels
extern __shared__ char s_raw[];

// ---------------- packed f32x2 helpers --------------------------------------
__device__ __forceinline__ u64 fma2(u64 a, u64 b, u64 c) {
    u64 d;
    asm("fma.rn.f32x2 %0, %1, %2, %3;" : "=l"(d) : "l"(a), "l"(b), "l"(c));
    return d;
}
__device__ __forceinline__ void unpack2(u64 v, float& lo, float& hi) {
    asm("mov.b64 {%0, %1}, %2;" : "=f"(lo), "=f"(hi) : "l"(v));
}

// multiply by (-i)^k
__device__ __forceinline__ float2 rot_negi(float2 x, int k) {
    switch (k & 3) {
        case 0: return x;
        case 1: return make_float2(x.y, -x.x);
        case 2: return make_float2(-x.x, -x.y);
        default: return make_float2(-x.y, x.x);
    }
}
// multiply by i^k
__device__ __forceinline__ float2 rot_posi(float2 x, int k) {
    switch (k & 3) {
        case 0: return x;
        case 1: return make_float2(-x.y, x.x);
        case 2: return make_float2(-x.x, -x.y);
        default: return make_float2(x.y, -x.x);
    }
}

// ---------------- scratch (device globals; no allocation allowed) -------------
__device__ float2 g_Bu[(size_t)NFX * FRAME];   // conv-B output
// Spectral arrays use the TRANSFORM-NATIVE layout:
//   idx = (p>>2)*4096 + (a*32 + c)*4 + (p&3)
__device__ float2 g_sp[(size_t)NF * FRAME];    // spectral b_elems -> scan output (in-place)
__device__ float2 g_x0t[(size_t)BB * FRAME];   // B_coeff * transform(B x0)
__device__ float2 g_xri[(size_t)NF * FRAME];   // (Re, Im) of x_sp, [hw][p] interleaved
__device__ float2 g_Abar[FRAME];               // transform-native layout
__device__ float2 g_Bcoef[FRAME];              // transform-native layout
__device__ float2 g_Sdup[1024];                // real DST matrix S[m][n], duplicated (s,s)
__device__ float4 g_Wb4[9 * 32 * 64];          // [tap][cp][p]
__device__ float4 g_Wc4[9 * 32 * 64];          // [tap][cp][uo]
__device__ float4 g_Wd4[9 * 16 * 64];          // [tap][cq][uo]

// ---------------- K0: S matrix + A_bar + B_coeff (merged) -------------------
__global__ void k_precompute_qab(const float* __restrict__ Lre,
                                 const float* __restrict__ Lim,
                                 const float* __restrict__ values,
                                 const float* __restrict__ log_step) {
    int idx = blockIdx.x * 256 + threadIdx.x;   // enumerates (a, c, p)

    if (idx < 1024) {
        int m = idx / 32 + 1, n = idx % 32 + 1;
        double s = sin(M_PI * (double)m * (double)n / 33.0) / sqrt(16.5);
        g_Sdup[idx] = make_float2((float)s, (float)s);
    }

    int p = idx & 63, w = (idx >> 6) & 31, h = idx >> 11;

    float v0 = values[p * 4 + 0], v1 = values[p * 4 + 1];
    float v2 = values[p * 4 + 2], v3 = values[p * 4 + 3];
    float mx = fmaxf(fmaxf(v0, v1), fmaxf(v2, v3));
    float e0 = expf(v0 - mx), e1 = expf(v1 - mx), e2 = expf(v2 - mx), e3 = expf(v3 - mx);
    float inv = 4.f / (e0 + e1 + e2 + e3);
    float xk = e0 * inv, yk = e1 * inv, zk = e2 * inv, wk = e3 * inv;
    float kv0 = (xk + yk - 2.f) * 0.25f;
    float kv1 = (xk + zk - 2.f) * 0.25f;
    float kv2 = (xk + wk - 2.f) * 0.125f;

    double ch = 2.0 * cos(M_PI * (double)(h + 1) / 33.0);
    double cw = 2.0 * cos(M_PI * (double)(w + 1) / 33.0);
    float Dv = kv0 * (float)cw + kv1 * (float)ch + kv2 * (float)(ch * cw) + 1.f;

    float lre = fminf(Lre[p], -1e-4f);
    float lim = Lim[p];
    float st = expf(log_step[p]);

    float tre = lre * Dv, tim = lim * Dv;
    float er = expf(tre * st);
    float Ar = er * cosf(tim * st);
    float Ai = er * sinf(tim * st);

    int nidx = ((p >> 2) << 12) + ((h * 32 + w) << 2) + (p & 3);
    g_Abar[nidx] = make_float2(Ar, Ai);

    float den = tre * tre + tim * tim;
    float br = ((Ar - 1.f) * tre + Ai * tim) / den;
    float bi = (Ai * tre - (Ar - 1.f) * tim) / den;
    g_Bcoef[nidx] = make_float2(br, bi);
}

// ---------------- weight packing (ci-pair float4) ----------------------------
__global__ void k_pack_b(const float* __restrict__ Br, const float* __restrict__ Bi) {
    int i = blockIdx.x * 256 + threadIdx.x;     // 0..18431 [tap][cp][p]
    int p = i & 63, cp = (i >> 6) & 31, tap = i >> 11;
    int i0 = (tap * 64 + 2 * cp) * 64 + p;
    g_Wb4[i] = make_float4(Br[i0], Bi[i0], Br[i0 + 64], Bi[i0 + 64]);
}
__global__ void k_pack_c(const float* __restrict__ Cr, const float* __restrict__ Ci) {
    int i = blockIdx.x * 256 + threadIdx.x;     // [tap][cp][uo]
    int uo = i & 63, cp = (i >> 6) & 31, tap = i >> 11;
    int i0 = (tap * 64 + 2 * cp) * 64 + uo;
    g_Wc4[i] = make_float4(2.f * Cr[i0], -2.f * Ci[i0],
                           2.f * Cr[i0 + 64], -2.f * Ci[i0 + 64]);
}
__global__ void k_pack_d(const float* __restrict__ Dk) {
    int i = blockIdx.x * 256 + threadIdx.x;     // 0..9215 [tap][cq][uo]
    int uo = i & 63, cq = (i >> 6) & 15, tap = i >> 10;
    int i0 = (tap * 64 + 4 * cq) * 64 + uo;
    g_Wd4[i] = make_float4(Dk[i0], Dk[i0 + 64], Dk[i0 + 128], Dk[i0 + 192]);
}

// ---------------- K1: conv B (complex, fma2, 2 output rows per block) -------
__global__ void __launch_bounds__(256, 2) conv_b_kernel(const float* __restrict__ u,
                                                        const float* __restrict__ x0) {
    int h0 = blockIdx.x * 2, f = blockIdx.y;
    const float* src = (f < NF) ? (u + (size_t)f * FRAME)
                                : (x0 + (size_t)(f - NF) * FRAME);
    float2* sdup = (float2*)s_raw;              // [4][34][64] duplicated values
    int t = threadIdx.x;
    for (int i = t; i < 4 * 34 * 64; i += 256) {
        int rr = i / 2176, rem = i % 2176;
        int wp = rem >> 6, ch = rem & 63;
        int hi = h0 - 1 + rr;
        float v = 0.f;
        if (hi >= 0 && hi < HH && wp >= 1 && wp <= 32)
            v = src[((size_t)hi * 32 + (wp - 1)) * 64 + ch];
        sdup[i] = make_float2(v, v);
    }
    __syncthreads();

    int p = t & 63, wg = t >> 6, w0 = wg * 8;
    u64 acc0[8], acc1[8];
#pragma unroll
    for (int j = 0; j < 8; j++) { acc0[j] = 0ull; acc1[j] = 0ull; }

    const ulonglong2* sd = (const ulonglong2*)sdup;   // [rr][wp][cp]
    const ulonglong2* wb = (const ulonglong2*)g_Wb4;
    for (int cp = 0; cp < 32; cp++) {
        ulonglong2 wv[9];
#pragma unroll
        for (int k = 0; k < 9; k++)
            wv[k] = __ldg(&wb[(k * 32 + cp) * 64 + p]);
#pragma unroll
        for (int rr = 0; rr < 4; rr++) {
            const ulonglong2* row = sd + (rr * 34 + w0) * 32;
            ulonglong2 xv[10];
#pragma unroll
            for (int m = 0; m < 10; m++) xv[m] = row[m * 32 + cp];
            if (rr < 3) {
#pragma unroll
                for (int dx = 0; dx < 3; dx++)
#pragma unroll
                    for (int j = 0; j < 8; j++) {
                        acc0[j] = fma2(xv[j + dx].x, wv[rr * 3 + dx].x, acc0[j]);
                        acc0[j] = fma2(xv[j + dx].y, wv[rr * 3 + dx].y, acc0[j]);
                    }
            }
            if (rr > 0) {
#pragma unroll
                for (int dx = 0; dx < 3; dx++)
#pragma unroll
                    for (int j = 0; j < 8; j++) {
                        acc1[j] = fma2(xv[j + dx].x, wv[(rr - 1) * 3 + dx].x, acc1[j]);
                        acc1[j] = fma2(xv[j + dx].y, wv[(rr - 1) * 3 + dx].y, acc1[j]);
                    }
            }
        }
    }
    u64* dst0 = (u64*)(g_Bu + (size_t)f * FRAME + (size_t)h0 * 32 * 64);
    u64* dst1 = dst0 + 32 * 64;
#pragma unroll
    for (int j = 0; j < 8; j++) {
        dst0[(w0 + j) * 64 + p] = acc0[j];
        dst1[(w0 + j) * 64 + p] = acc1[j];
    }
}

// ---------------- K2: forward transform (conflict-free, Ms aliases Xs) ------
// smem: Xs/Ms alias [4096 f2] + Sd [1024 f2] = 40960 B -> 4 blocks/SM.
// Safe: warp wg reads ONLY rows h = wg mod 4 of Xs (accumulated in regs over
// the full w loop) and then writes Ms rows with the same h set; cross-warp
// consumption happens only after __syncthreads.
__global__ void __launch_bounds__(128, 4) fwd_transform_kernel() {
    float2* Xs = (float2*)s_raw;        // [hw][j] 4096, reused as Ms
    float2* Sd = Xs + 4096;             // 1024
    int f = blockIdx.y;
    int p0 = blockIdx.x * 4;
    int t = threadIdx.x;

    for (int i = t; i < 1024; i += 128) Sd[i] = g_Sdup[i];
    // vectorized fill: one 16B load = 2 consecutive j (same rotation factor)
    const ulonglong2* src2 = (const ulonglong2*)(g_Bu + (size_t)f * FRAME + p0);
    ulonglong2* Xs2 = (ulonglong2*)Xs;
    for (int i = t; i < 2048; i += 128) {
        int j2 = i & 1, hw = i >> 1;
        int h = hw >> 5, w = hw & 31;
        ulonglong2 v = src2[hw * 32 + j2];
        float2 a = ((float2*)&v)[0], b = ((float2*)&v)[1];
        int k = h + w + 2;
        a = rot_negi(a, k);
        b = rot_negi(b, k);
        ulonglong2 o;
        ((float2*)&o)[0] = a;
        ((float2*)&o)[1] = b;
        Xs2[i] = o;
    }
    __syncthreads();

    int wg = t >> 5;
    int c5 = (t & 31) >> 2, j = t & 3;
    const u64* sXs = (const u64*)Xs;
    const u64* sSd = (const u64*)Sd;
    u64* sMs = (u64*)Xs;               // alias

    {   // pass1: M[h][c][j] = sum_w X'[h][w][j] * S[w][c]
        u64 acc[8][4];
#pragma unroll
        for (int a1 = 0; a1 < 8; a1++)
#pragma unroll
            for (int a2 = 0; a2 < 4; a2++) acc[a1][a2] = 0ull;

        for (int w = 0; w < 32; w++) {
            u64 sv[4];
#pragma unroll
            for (int cc = 0; cc < 4; cc++) sv[cc] = sSd[w * 32 + c5 + 8 * cc];
            u64 xv[8];
#pragma unroll
            for (int hh = 0; hh < 8; hh++)
                xv[hh] = sXs[(((wg + 4 * hh) * 32 + w) << 2) + j];
#pragma unroll
            for (int hh = 0; hh < 8; hh++)
#pragma unroll
                for (int cc = 0; cc < 4; cc++)
                    acc[hh][cc] = fma2(xv[hh], sv[cc], acc[hh][cc]);
        }
        __syncwarp();
#pragma unroll
        for (int hh = 0; hh < 8; hh++)
#pragma unroll
            for (int cc = 0; cc < 4; cc++)
                sMs[(((wg + 4 * hh) * 32 + c5 + 8 * cc) << 2) + j] = acc[hh][cc];
    }
    __syncthreads();

    bool isx0 = (f >= NF);
    float2* dst = isx0 ? g_x0t : g_sp;
    size_t base = isx0 ? (size_t)(f - NF) * FRAME : (size_t)f * FRAME;

    {   // pass2: out[a][c][j] = sum_h S[h][a] * M[h][c][j]
        u64 acc[8][4];
#pragma unroll
        for (int a1 = 0; a1 < 8; a1++)
#pragma unroll
            for (int a2 = 0; a2 < 4; a2++) acc[a1][a2] = 0ull;

        for (int h = 0; h < 32; h++) {
            u64 sv[8];
#pragma unroll
            for (int aa = 0; aa < 8; aa++) sv[aa] = sSd[h * 32 + wg + 4 * aa];
            u64 mv[4];
#pragma unroll
            for (int cc = 0; cc < 4; cc++)
                mv[cc] = sMs[((h * 32 + c5 + 8 * cc) << 2) + j];
#pragma unroll
            for (int aa = 0; aa < 8; aa++)
#pragma unroll
                for (int cc = 0; cc < 4; cc++)
                    acc[aa][cc] = fma2(mv[cc], sv[aa], acc[aa][cc]);
        }
        int pbase = p0 * 1024;
#pragma unroll
        for (int aa = 0; aa < 8; aa++)
#pragma unroll
            for (int cc = 0; cc < 4; cc++) {
                int a = wg + 4 * aa, c = c5 + 8 * cc;
                int idx = pbase + ((a * 32 + c) << 2) + j;
                float xr, xi;
                unpack2(acc[aa][cc], xr, xi);
                float2 bc = g_Bcoef[idx];
                dst[base + idx] = make_float2(xr * bc.x - xi * bc.y,
                                              xr * bc.y + xi * bc.x);
            }
    }
}

// ---------------- K3: linear recurrence over L (vectorized x2, in place) ----
__global__ void scan_kernel() {
    int idx = blockIdx.x * 256 + threadIdx.x;   // (b, element-pair)
    int b = idx >> 15;
    int ap = idx & 32767;
    float4 A = ((const float4*)g_Abar)[ap];
    float4 x = ((const float4*)g_x0t)[((size_t)b << 15) + ap];
    float4* sp4 = (float4*)g_sp;
    for (int l = 0; l < LL; l++) {
        size_t off = ((size_t)(l * BB + b) << 15) + ap;
        float4 v = sp4[off];
        float4 nx;
        nx.x = A.x * x.x - A.y * x.y + v.x;
        nx.y = A.x * x.y + A.y * x.x + v.y;
        nx.z = A.z * x.z - A.w * x.w + v.z;
        nx.w = A.z * x.w + A.w * x.z + v.w;
        x = nx;
        sp4[off] = x;
    }
}

// ---------------- K4: inverse transform (conflict-free, Ms aliases Xs) ------
__global__ void __launch_bounds__(128, 4) inv_transform_kernel() {
    float2* Xs = (float2*)s_raw;        // [ac][j], reused as Ms
    float2* Sd = Xs + 4096;
    int f = blockIdx.y;
    int p0 = blockIdx.x * 4;
    int t = threadIdx.x;

    for (int i = t; i < 1024; i += 128) Sd[i] = g_Sdup[i];
    const float4* src4 = (const float4*)(g_sp + (size_t)f * FRAME + (size_t)p0 * 1024);
    float4* Xs4 = (float4*)Xs;
    for (int i = t; i < 2048; i += 128) Xs4[i] = src4[i];
    __syncthreads();

    int wg = t >> 5;
    int w5 = (t & 31) >> 2, j = t & 3;
    const u64* sXs = (const u64*)Xs;
    const u64* sSd = (const u64*)Sd;
    u64* sMs = (u64*)Xs;               // alias

    {   // pass1: Y[a][w][j] = sum_c X[a][c][j] * S[w][c]
        u64 acc[8][4];
#pragma unroll
        for (int a1 = 0; a1 < 8; a1++)
#pragma unroll
            for (int a2 = 0; a2 < 4; a2++) acc[a1][a2] = 0ull;

        for (int c = 0; c < 32; c++) {
            u64 sv[4];
#pragma unroll
            for (int wc = 0; wc < 4; wc++) sv[wc] = sSd[c * 32 + w5 + 8 * wc];
            u64 xv[8];
#pragma unroll
            for (int aa = 0; aa < 8; aa++)
                xv[aa] = sXs[(((wg + 4 * aa) * 32 + c) << 2) + j];
#pragma unroll
            for (int aa = 0; aa < 8; aa++)
#pragma unroll
                for (int wc = 0; wc < 4; wc++)
                    acc[aa][wc] = fma2(xv[aa], sv[wc], acc[aa][wc]);
        }
        __syncwarp();
#pragma unroll
        for (int aa = 0; aa < 8; aa++)
#pragma unroll
            for (int wc = 0; wc < 4; wc++)
                sMs[(((wg + 4 * aa) * 32 + w5 + 8 * wc) << 2) + j] = acc[aa][wc];
    }
    __syncthreads();

    float2* xri = g_xri + (size_t)f * FRAME;
    {   // pass2: out[h][w][j] = i^{h+w+2} * sum_a S[h][a] * Y[a][w][j]
        u64 acc[8][4];
#pragma unroll
        for (int a1 = 0; a1 < 8; a1++)
#pragma unroll
            for (int a2 = 0; a2 < 4; a2++) acc[a1][a2] = 0ull;

        for (int a = 0; a < 32; a++) {
            u64 sv[8];
#pragma unroll
            for (int hh = 0; hh < 8; hh++) sv[hh] = sSd[a * 32 + wg + 4 * hh];
            u64 mv[4];
#pragma unroll
            for (int wc = 0; wc < 4; wc++)
                mv[wc] = sMs[((a * 32 + w5 + 8 * wc) << 2) + j];
#pragma unroll
            for (int hh = 0; hh < 8; hh++)
#pragma unroll
                for (int wc = 0; wc < 4; wc++)
                    acc[hh][wc] = fma2(mv[wc], sv[hh], acc[hh][wc]);
        }
#pragma unroll
        for (int hh = 0; hh < 8; hh++)
#pragma unroll
            for (int wc = 0; wc < 4; wc++) {
                int h = wg + 4 * hh, w = w5 + 8 * wc;
                float xr, xi;
                unpack2(acc[hh][wc], xr, xi);
                float2 v = rot_posi(make_float2(xr, xi), h + w + 2);
                xri[(size_t)(h * 32 + w) * 64 + p0 + j] = v;
            }
    }
}

// ---------------- K5: conv C then conv D (sequential phases) + GELU ---------
__global__ void __launch_bounds__(256, 2) conv_cd_kernel(const float* __restrict__ u,
                                                         float* __restrict__ out) {
    int h0 = blockIdx.x * 2, f = blockIdx.y;
    int t = threadIdx.x;
    int uo = t & 63, wg = t >> 6, w0 = wg * 8;

    u64 acc0[8], acc1[8];
#pragma unroll
    for (int j = 0; j < 8; j++) { acc0[j] = 0ull; acc1[j] = 0ull; }

    // ---- Phase C ----
    {
        float2* sxri = (float2*)s_raw;          // [4][34][64]
        const float2* src = g_xri + (size_t)f * FRAME;
        for (int i = t; i < 4 * 34 * 64; i += 256) {
            int rr = i / 2176, rem = i % 2176;
            int wp = rem >> 6, ch = rem & 63;
            int hi = h0 - 1 + rr;
            bool valid = (hi >= 0 && hi < HH && wp >= 1 && wp <= 32);
            sxri[i] = valid ? src[((size_t)hi * 32 + (wp - 1)) * 64 + ch]
                            : make_float2(0.f, 0.f);
        }
        __syncthreads();

        const ulonglong2* sx = (const ulonglong2*)sxri;   // [rr][wp][cp]
        const ulonglong2* wc = (const ulonglong2*)g_Wc4;
        for (int cp = 0; cp < 32; cp++) {
            ulonglong2 wv[9];
#pragma unroll
            for (int k = 0; k < 9; k++)
                wv[k] = __ldg(&wc[(k * 32 + cp) * 64 + uo]);
#pragma unroll
            for (int rr = 0; rr < 4; rr++) {
                const ulonglong2* row = sx + (rr * 34 + w0) * 32;
                ulonglong2 xv[10];
#pragma unroll
                for (int m = 0; m < 10; m++) xv[m] = row[m * 32 + cp];
                if (rr < 3) {
#pragma unroll
                    for (int dx = 0; dx < 3; dx++)
#pragma unroll
                        for (int j = 0; j < 8; j++) {
                            acc0[j] = fma2(xv[j + dx].x, wv[rr * 3 + dx].x, acc0[j]);
                            acc0[j] = fma2(xv[j + dx].y, wv[rr * 3 + dx].y, acc0[j]);
                        }
                }
                if (rr > 0) {
#pragma unroll
                    for (int dx = 0; dx < 3; dx++)
#pragma unroll
                        for (int j = 0; j < 8; j++) {
                            acc1[j] = fma2(xv[j + dx].x, wv[(rr - 1) * 3 + dx].x, acc1[j]);
                            acc1[j] = fma2(xv[j + dx].y, wv[(rr - 1) * 3 + dx].y, acc1[j]);
                        }
                }
            }
        }
    }
    __syncthreads();   // all reads of sxri done before overwrite

    // ---- Phase D ----
    {
        float* su = (float*)s_raw;              // [4][34][64] (reuses same smem)
        const float* u_src = u + (size_t)f * FRAME;
        for (int i = t; i < 4 * 34 * 64; i += 256) {
            int rr = i / 2176, rem = i % 2176;
            int wp = rem >> 6, ch = rem & 63;
            int hi = h0 - 1 + rr;
            bool valid = (hi >= 0 && hi < HH && wp >= 1 && wp <= 32);
            su[i] = valid ? u_src[((size_t)hi * 32 + (wp - 1)) * 64 + ch] : 0.f;
        }
        __syncthreads();

        const ulonglong2* sup = (const ulonglong2*)su;    // [rr][wp][cq]
        const ulonglong2* wd = (const ulonglong2*)g_Wd4;
        for (int cq = 0; cq < 16; cq++) {
            ulonglong2 wv[9];
#pragma unroll
            for (int k = 0; k < 9; k++)
                wv[k] = __ldg(&wd[(k * 16 + cq) * 64 + uo]);
#pragma unroll
            for (int rr = 0; rr < 4; rr++) {
                const ulonglong2* row = sup + (rr * 34 + w0) * 16;
                ulonglong2 uv[10];
#pragma unroll
                for (int m = 0; m < 10; m++) uv[m] = row[m * 16 + cq];
                if (rr < 3) {
#pragma unroll
                    for (int dx = 0; dx < 3; dx++)
#pragma unroll
                        for (int j = 0; j < 8; j++) {
                            acc0[j] = fma2(uv[j + dx].x, wv[rr * 3 + dx].x, acc0[j]);
                            acc0[j] = fma2(uv[j + dx].y, wv[rr * 3 + dx].y, acc0[j]);
                        }
                }
                if (rr > 0) {
#pragma unroll
                    for (int dx = 0; dx < 3; dx++)
#pragma unroll
                        for (int j = 0; j < 8; j++) {
                            acc1[j] = fma2(uv[j + dx].x, wv[(rr - 1) * 3 + dx].x, acc1[j]);
                            acc1[j] = fma2(uv[j + dx].y, wv[(rr - 1) * 3 + dx].y, acc1[j]);
                        }
                }
            }
        }
    }

    size_t base0 = (size_t)f * FRAME + (size_t)h0 * 32 * 64;
    size_t base1 = base0 + 32 * 64;
#pragma unroll
    for (int j = 0; j < 8; j++) {
        float lo, hi;
        unpack2(acc0[j], lo, hi);
        float x = lo + hi;
        float inner = 0.7978845608028654f * (x + 0.044715f * x * x * x);
        out[base0 + (w0 + j) * 64 + uo] = 0.5f * x * (1.f + tanhf(inner));
        unpack2(acc1[j], lo, hi);
        x = lo + hi;
        inner = 0.7978845608028654f * (x + 0.044715f * x * x * x);
        out[base1 + (w0 + j) * 64 + uo] = 0.5f * x * (1.f + tanhf(inner));
    }
}

// ---------------- launch ----------------------------------------------------
extern "C" void kernel_launch(void* const* d_in, const int* in_sizes, int n_in,
                              void* d_out, int out_size) {
    const float* u        = (const float*)d_in[0];
    const float* x0       = (const float*)d_in[1];
    const float* Lre      = (const float*)d_in[2];
    const float* Lim      = (const float*)d_in[3];
    const float* values   = (const float*)d_in[4];
    const float* log_step = (const float*)d_in[5];
    const float* Br       = (const float*)d_in[6];
    const float* Bi       = (const float*)d_in[7];
    const float* Cr       = (const float*)d_in[8];
    const float* Ci       = (const float*)d_in[9];
    const float* Dk       = (const float*)d_in[10];
    float* out = (float*)d_out;

    static const size_t TSM = (4096 + 1024) * sizeof(float2);          // 40960 B
    static const size_t BSM = 4 * 34 * 64 * sizeof(float2);            // 69632 B
    static const size_t CSM = 4 * 34 * 64 * sizeof(float2);            // 69632 B
    cudaFuncSetAttribute(fwd_transform_kernel, cudaFuncAttributeMaxDynamicSharedMemorySize, (int)TSM);
    cudaFuncSetAttribute(inv_transform_kernel, cudaFuncAttributeMaxDynamicSharedMemorySize, (int)TSM);
    cudaFuncSetAttribute(conv_b_kernel,        cudaFuncAttributeMaxDynamicSharedMemorySize, (int)BSM);
    cudaFuncSetAttribute(conv_cd_kernel,       cudaFuncAttributeMaxDynamicSharedMemorySize, (int)CSM);

    // fwd_transform is the 4th launch (ncu captures launch #4).
    k_pack_b<<<72, 256>>>(Br, Bi);
    conv_b_kernel<<<dim3(16, NFX), 256, BSM>>>(u, x0);
    k_precompute_qab<<<256, 256>>>(Lre, Lim, values, log_step);
    fwd_transform_kernel<<<dim3(16, NFX), 128, TSM>>>();
    k_pack_c<<<72, 256>>>(Cr, Ci);
    k_pack_d<<<36, 256>>>(Dk);
    scan_kernel<<<1024, 256>>>();
    inv_transform_kernel<<<dim3(16, NF), 128, TSM>>>();
    conv_cd_kernel<<<dim3(16, NF), 256, CSM>>>(u, out);
    (void)in_sizes; (void)n_in; (void)out_size;
}